// round 1
// baseline (speedup 1.0000x reference)
#include <cuda_runtime.h>
#include <math.h>

#define B_    2
#define S_    2048
#define HID_  2048
#define NH_   16
#define QLR_  1536
#define KVLR_ 512
#define DN_   128
#define DR_   64
#define DV_   128
#define DQK_  192
#define MTOT  (B_ * S_)            // 4096
#define CKVW  (KVLR_ + DR_)        // 576
#define QW    (NH_ * DQK_)         // 3072
#define KVW   (NH_ * (DN_ + DV_))  // 4096
#define AOW   (NH_ * DV_)          // 2048
#define SCALE_CONST 0.07216878364870322f   // 192^-0.5

// ---------------- scratch (no allocation allowed) ----------------
__device__ float g_qa [(size_t)MTOT * QLR_];
__device__ float g_ckv[(size_t)MTOT * CKVW];
__device__ float g_q  [(size_t)MTOT * QW];
__device__ float g_kv [(size_t)MTOT * KVW];
__device__ float g_ao [(size_t)MTOT * AOW];

// ---------------- generic tiled GEMM: C[M,N] = A[M,K] @ Bm[K,N] ----------------
// BM=128 BN=128 BK=8, 256 threads, 8x8 per-thread tile.
__global__ __launch_bounds__(256) void gemm_kernel(
    const float* __restrict__ A, int lda,
    const float* __restrict__ Bm, int ldb,
    float* __restrict__ C, int ldc,
    int M, int N, int K)
{
    __shared__ float As[8][128];
    __shared__ float Bs[8][128];

    int tid = threadIdx.x;
    int m0 = blockIdx.y * 128, n0 = blockIdx.x * 128;
    int ty = tid >> 4, tx = tid & 15;

    float acc[8][8];
#pragma unroll
    for (int i = 0; i < 8; i++)
#pragma unroll
        for (int j = 0; j < 8; j++) acc[i][j] = 0.f;

    int arow = tid >> 1, akq = (tid & 1) * 4;
    int bkr = tid >> 5, bc = (tid & 31) * 4;

    for (int k0 = 0; k0 < K; k0 += 8) {
        // load A tile (always in-bounds: M%128==0, K%8==0)
        float4 a4 = *(const float4*)&A[(size_t)(m0 + arow) * lda + k0 + akq];
        As[akq + 0][arow] = a4.x;
        As[akq + 1][arow] = a4.y;
        As[akq + 2][arow] = a4.z;
        As[akq + 3][arow] = a4.w;
        // load B tile (guard N)
        float4 b4 = make_float4(0.f, 0.f, 0.f, 0.f);
        if (n0 + bc < N) b4 = *(const float4*)&Bm[(size_t)(k0 + bkr) * ldb + n0 + bc];
        *(float4*)&Bs[bkr][bc] = b4;
        __syncthreads();

#pragma unroll
        for (int k = 0; k < 8; k++) {
            float a[8], b[8];
            *(float4*)(a)     = *(const float4*)&As[k][ty * 8];
            *(float4*)(a + 4) = *(const float4*)&As[k][ty * 8 + 4];
            *(float4*)(b)     = *(const float4*)&Bs[k][tx * 8];
            *(float4*)(b + 4) = *(const float4*)&Bs[k][tx * 8 + 4];
#pragma unroll
            for (int i = 0; i < 8; i++)
#pragma unroll
                for (int j = 0; j < 8; j++) acc[i][j] += a[i] * b[j];
        }
        __syncthreads();
    }

#pragma unroll
    for (int i = 0; i < 8; i++) {
        int row = m0 + ty * 8 + i;
#pragma unroll
        for (int jq = 0; jq < 8; jq += 4) {
            int col = n0 + tx * 8 + jq;
            if (col < N) {
                float4 v = make_float4(acc[i][jq], acc[i][jq + 1], acc[i][jq + 2], acc[i][jq + 3]);
                *(float4*)&C[(size_t)row * ldc + col] = v;
            }
        }
    }
}

// ---------------- rmsnorm (in place), one block per row ----------------
__global__ __launch_bounds__(256) void rmsnorm_kernel(float* __restrict__ x, int stride, int D,
                                                      const float* __restrict__ w)
{
    int row = blockIdx.x;
    float* p = x + (size_t)row * stride;
    float ss = 0.f;
    for (int i = threadIdx.x; i < D; i += 256) { float v = p[i]; ss += v * v; }
    __shared__ float red[8];
#pragma unroll
    for (int off = 16; off; off >>= 1) ss += __shfl_down_sync(0xffffffffu, ss, off);
    if ((threadIdx.x & 31) == 0) red[threadIdx.x >> 5] = ss;
    __syncthreads();
    if (threadIdx.x == 0) {
        float t = 0.f;
#pragma unroll
        for (int i = 0; i < 8; i++) t += red[i];
        red[0] = rsqrtf(t / (float)D + 1e-6f);
    }
    __syncthreads();
    float inv = red[0];
    for (int i = threadIdx.x; i < D; i += 256) p[i] = p[i] * inv * w[i];
}

// ---------------- RoPE ----------------
__global__ void rope_q_kernel(float* __restrict__ q, const float* __restrict__ cosb,
                              const float* __restrict__ sinb)
{
    int idx = blockIdx.x * blockDim.x + threadIdx.x;
    if (idx >= MTOT * NH_ * 32) return;
    int j = idx & 31;
    int h = (idx >> 5) & (NH_ - 1);
    int m = idx >> 9;
    int s = m & (S_ - 1);
    float* base = q + (size_t)m * QW + h * DQK_ + DN_;
    float x = base[j], y = base[j + 32];
    float c0 = cosb[s * DR_ + j],      s0 = sinb[s * DR_ + j];
    float c1 = cosb[s * DR_ + j + 32], s1 = sinb[s * DR_ + j + 32];
    base[j]      = x * c0 - y * s0;
    base[j + 32] = y * c1 + x * s1;
}

__global__ void rope_k_kernel(float* __restrict__ ckv, const float* __restrict__ cosb,
                              const float* __restrict__ sinb)
{
    int idx = blockIdx.x * blockDim.x + threadIdx.x;
    if (idx >= MTOT * 32) return;
    int j = idx & 31;
    int m = idx >> 5;
    int s = m & (S_ - 1);
    float* base = ckv + (size_t)m * CKVW + KVLR_;
    float x = base[j], y = base[j + 32];
    float c0 = cosb[s * DR_ + j],      s0 = sinb[s * DR_ + j];
    float c1 = cosb[s * DR_ + j + 32], s1 = sinb[s * DR_ + j + 32];
    base[j]      = x * c0 - y * s0;
    base[j + 32] = y * c1 + x * s1;
}

// ---------------- flash attention ----------------
// grid (32, NH, B); 256 threads; 64 q-rows x 64 k-cols per tile; d_qk=192, d_v=128.
#define QT_LD 68
#define V_LD  132
#define P_LD  68
#define ATTN_SMEM_FLOATS (192 * QT_LD * 2 + 64 * V_LD + 64 * P_LD + 192)
#define ATTN_SMEM_BYTES  (ATTN_SMEM_FLOATS * 4)

__global__ __launch_bounds__(256) void attn_kernel(
    const float* __restrict__ q, const float* __restrict__ kv,
    const float* __restrict__ ckv, float* __restrict__ ao)
{
    extern __shared__ float sm[];
    float* Qt   = sm;                   // [192][68] (d-major, transposed)
    float* Kt   = Qt + 192 * QT_LD;     // [192][68]
    float* Vs   = Kt + 192 * QT_LD;     // [64][132]
    float* Pt   = Vs + 64 * V_LD;       // [64][68]  Pt[kc][qr]
    float* mrow = Pt + 64 * P_LD;       // [64]
    float* lrow = mrow + 64;            // [64]
    float* arow = lrow + 64;            // [64]

    int qt = blockIdx.x, h = blockIdx.y, b = blockIdx.z;
    int tid = threadIdx.x, ty = tid >> 4, tx = tid & 15;
    int qr0 = ty * 4, kc0 = tx * 4, vd0 = tx * 8;

    // load Q tile (scaled)
    for (int idx = tid; idx < 64 * 192; idx += 256) {
        int qr = idx / 192, d = idx - qr * 192;
        Qt[d * QT_LD + qr] =
            q[(size_t)(b * S_ + qt * 64 + qr) * QW + h * DQK_ + d] * SCALE_CONST;
    }
    if (tid < 64) { mrow[tid] = -1e30f; lrow[tid] = 0.f; }

    float o[4][8];
#pragma unroll
    for (int i = 0; i < 4; i++)
#pragma unroll
        for (int j = 0; j < 8; j++) o[i][j] = 0.f;

    __syncthreads();

    for (int kt = 0; kt <= qt; kt++) {
        int kbase = b * S_ + kt * 64;
        // load K tile (k_nope from kv, k_pe from roped ckv)
        for (int idx = tid; idx < 64 * 192; idx += 256) {
            int kc = idx / 192, d = idx - kc * 192;
            float v = (d < 128)
                ? kv[(size_t)(kbase + kc) * KVW + h * 256 + d]
                : ckv[(size_t)(kbase + kc) * CKVW + KVLR_ + (d - 128)];
            Kt[d * QT_LD + kc] = v;
        }
        // load V tile
        for (int idx = tid; idx < 64 * 128; idx += 256) {
            int kc = idx >> 7, d = idx & 127;
            Vs[kc * V_LD + d] = kv[(size_t)(kbase + kc) * KVW + h * 256 + 128 + d];
        }
        __syncthreads();

        // scores: S[qr][kc] = sum_d Qt[d][qr]*Kt[d][kc]
        float s4[4][4];
#pragma unroll
        for (int i = 0; i < 4; i++)
#pragma unroll
            for (int j = 0; j < 4; j++) s4[i][j] = 0.f;
#pragma unroll 4
        for (int d = 0; d < 192; d++) {
            float4 a = *(const float4*)&Qt[d * QT_LD + qr0];
            float4 bb = *(const float4*)&Kt[d * QT_LD + kc0];
            s4[0][0] += a.x * bb.x; s4[0][1] += a.x * bb.y; s4[0][2] += a.x * bb.z; s4[0][3] += a.x * bb.w;
            s4[1][0] += a.y * bb.x; s4[1][1] += a.y * bb.y; s4[1][2] += a.y * bb.z; s4[1][3] += a.y * bb.w;
            s4[2][0] += a.z * bb.x; s4[2][1] += a.z * bb.y; s4[2][2] += a.z * bb.z; s4[2][3] += a.z * bb.w;
            s4[3][0] += a.w * bb.x; s4[3][1] += a.w * bb.y; s4[3][2] += a.w * bb.z; s4[3][3] += a.w * bb.w;
        }
        if (kt == qt) {
#pragma unroll
            for (int i = 0; i < 4; i++)
#pragma unroll
                for (int j = 0; j < 4; j++)
                    if (kc0 + j > qr0 + i) s4[i][j] = -1e30f;
        }
#pragma unroll
        for (int i = 0; i < 4; i++)
#pragma unroll
            for (int j = 0; j < 4; j++)
                Pt[(kc0 + j) * P_LD + (qr0 + i)] = s4[i][j];
        __syncthreads();

        // online softmax row pass
        if (tid < 64) {
            int qr = tid;
            float mo = mrow[qr], rm = mo;
#pragma unroll 4
            for (int kc = 0; kc < 64; kc++) rm = fmaxf(rm, Pt[kc * P_LD + qr]);
            float sum = 0.f;
#pragma unroll 4
            for (int kc = 0; kc < 64; kc++) {
                float p = __expf(Pt[kc * P_LD + qr] - rm);
                Pt[kc * P_LD + qr] = p;
                sum += p;
            }
            float al = __expf(mo - rm);
            lrow[qr] = lrow[qr] * al + sum;
            mrow[qr] = rm;
            arow[qr] = al;
        }
        __syncthreads();

        // rescale accumulators, then O += P @ V
#pragma unroll
        for (int i = 0; i < 4; i++) {
            float al = arow[qr0 + i];
#pragma unroll
            for (int j = 0; j < 8; j++) o[i][j] *= al;
        }
#pragma unroll 2
        for (int kc = 0; kc < 64; kc++) {
            float4 p  = *(const float4*)&Pt[kc * P_LD + qr0];
            float4 v0 = *(const float4*)&Vs[kc * V_LD + vd0];
            float4 v1 = *(const float4*)&Vs[kc * V_LD + vd0 + 4];
            o[0][0] += p.x * v0.x; o[0][1] += p.x * v0.y; o[0][2] += p.x * v0.z; o[0][3] += p.x * v0.w;
            o[0][4] += p.x * v1.x; o[0][5] += p.x * v1.y; o[0][6] += p.x * v1.z; o[0][7] += p.x * v1.w;
            o[1][0] += p.y * v0.x; o[1][1] += p.y * v0.y; o[1][2] += p.y * v0.z; o[1][3] += p.y * v0.w;
            o[1][4] += p.y * v1.x; o[1][5] += p.y * v1.y; o[1][6] += p.y * v1.z; o[1][7] += p.y * v1.w;
            o[2][0] += p.z * v0.x; o[2][1] += p.z * v0.y; o[2][2] += p.z * v0.z; o[2][3] += p.z * v0.w;
            o[2][4] += p.z * v1.x; o[2][5] += p.z * v1.y; o[2][6] += p.z * v1.z; o[2][7] += p.z * v1.w;
            o[3][0] += p.w * v0.x; o[3][1] += p.w * v0.y; o[3][2] += p.w * v0.z; o[3][3] += p.w * v0.w;
            o[3][4] += p.w * v1.x; o[3][5] += p.w * v1.y; o[3][6] += p.w * v1.z; o[3][7] += p.w * v1.w;
        }
        __syncthreads();
    }

    // epilogue
#pragma unroll
    for (int i = 0; i < 4; i++) {
        float inv = 1.f / lrow[qr0 + i];
        size_t row = (size_t)(b * S_ + qt * 64 + qr0 + i);
        float4 r0 = make_float4(o[i][0] * inv, o[i][1] * inv, o[i][2] * inv, o[i][3] * inv);
        float4 r1 = make_float4(o[i][4] * inv, o[i][5] * inv, o[i][6] * inv, o[i][7] * inv);
        *(float4*)&ao[row * AOW + h * DV_ + vd0]     = r0;
        *(float4*)&ao[row * AOW + h * DV_ + vd0 + 4] = r1;
    }
}

// ---------------- launch ----------------
extern "C" void kernel_launch(void* const* d_in, const int* in_sizes, int n_in,
                              void* d_out, int out_size)
{
    const float* hidden = (const float*)d_in[0];
    // d_in[1] = attention_mask (pure causal; applied analytically)
    const float* cosb   = (const float*)d_in[2];
    const float* sinb   = (const float*)d_in[3];
    const float* w_qa   = (const float*)d_in[4];
    const float* qa_ln  = (const float*)d_in[5];
    const float* w_qb   = (const float*)d_in[6];
    const float* w_kva  = (const float*)d_in[7];
    const float* kva_ln = (const float*)d_in[8];
    const float* w_kvb  = (const float*)d_in[9];
    const float* w_o    = (const float*)d_in[10];
    float* out = (float*)d_out;

    float *qa, *ckv, *qbuf, *kvbuf, *ao;
    cudaGetSymbolAddress((void**)&qa,    g_qa);
    cudaGetSymbolAddress((void**)&ckv,   g_ckv);
    cudaGetSymbolAddress((void**)&qbuf,  g_q);
    cudaGetSymbolAddress((void**)&kvbuf, g_kv);
    cudaGetSymbolAddress((void**)&ao,    g_ao);

    cudaFuncSetAttribute(attn_kernel, cudaFuncAttributeMaxDynamicSharedMemorySize,
                         ATTN_SMEM_BYTES);

    // 1. q_a = hidden @ w_qa
    gemm_kernel<<<dim3(QLR_ / 128, MTOT / 128), 256>>>(hidden, HID_, w_qa, QLR_, qa, QLR_,
                                                       MTOT, QLR_, HID_);
    // 2. ckv = hidden @ w_kva
    gemm_kernel<<<dim3((CKVW + 127) / 128, MTOT / 128), 256>>>(hidden, HID_, w_kva, CKVW,
                                                               ckv, CKVW, MTOT, CKVW, HID_);
    // 3. rmsnorm(q_a), rmsnorm(k_c)
    rmsnorm_kernel<<<MTOT, 256>>>(qa, QLR_, QLR_, qa_ln);
    rmsnorm_kernel<<<MTOT, 256>>>(ckv, CKVW, KVLR_, kva_ln);
    // 4. q = q_a_norm @ w_qb
    gemm_kernel<<<dim3(QW / 128, MTOT / 128), 256>>>(qa, QLR_, w_qb, QW, qbuf, QW,
                                                     MTOT, QW, QLR_);
    // 5. kv = k_c_norm @ w_kvb
    gemm_kernel<<<dim3(KVW / 128, MTOT / 128), 256>>>(ckv, CKVW, w_kvb, KVW, kvbuf, KVW,
                                                      MTOT, KVW, KVLR_);
    // 6. RoPE
    rope_q_kernel<<<(MTOT * NH_ * 32 + 255) / 256, 256>>>(qbuf, cosb, sinb);
    rope_k_kernel<<<(MTOT * 32 + 255) / 256, 256>>>(ckv, cosb, sinb);
    // 7. attention
    attn_kernel<<<dim3(S_ / 64, NH_, B_), 256, ATTN_SMEM_BYTES>>>(qbuf, kvbuf, ckv, ao);
    // 8. out = ao @ w_o
    gemm_kernel<<<dim3(HID_ / 128, MTOT / 128), 256>>>(ao, AOW, w_o, HID_, out, HID_,
                                                       MTOT, HID_, AOW);
}

// round 2
// speedup vs baseline: 1.5021x; 1.5021x over previous
#include <cuda_runtime.h>
#include <math.h>
#include <stdint.h>

#define B_    2
#define S_    2048
#define HID_  2048
#define NH_   16
#define QLR_  1536
#define KVLR_ 512
#define DN_   128
#define DR_   64
#define DV_   128
#define DQK_  192
#define MTOT  (B_ * S_)            // 4096
#define CKVW  (KVLR_ + DR_)        // 576
#define QW    (NH_ * DQK_)         // 3072
#define KVW   (NH_ * (DN_ + DV_))  // 4096
#define AOW   (NH_ * DV_)          // 2048
#define SCALE_CONST 0.07216878364870322f   // 192^-0.5

// ---------------- scratch (no allocation allowed) ----------------
__device__ float g_qa [(size_t)MTOT * QLR_];
__device__ float g_ckv[(size_t)MTOT * CKVW];
__device__ float g_q  [(size_t)MTOT * QW];
__device__ float g_kv [(size_t)MTOT * KVW];
__device__ float g_ao [(size_t)MTOT * AOW];

// ---------------- tf32 mma helpers ----------------
__device__ __forceinline__ uint32_t f2tf(float f) {
    uint32_t u;
    asm("cvt.rna.tf32.f32 %0, %1;" : "=r"(u) : "f"(f));
    return u;
}

__device__ __forceinline__ void ldsm4(uint32_t* r, uint32_t addr) {
    asm volatile("ldmatrix.sync.aligned.m8n8.x4.shared.b16 {%0,%1,%2,%3},[%4];"
                 : "=r"(r[0]), "=r"(r[1]), "=r"(r[2]), "=r"(r[3]) : "r"(addr));
}

__device__ __forceinline__ void mma_tf32(float4& d, const uint32_t* a, const uint32_t* b) {
    asm volatile("mma.sync.aligned.m16n8k8.row.col.f32.tf32.tf32.f32 "
                 "{%0,%1,%2,%3},{%4,%5,%6,%7},{%8,%9},{%0,%1,%2,%3};"
                 : "+f"(d.x), "+f"(d.y), "+f"(d.z), "+f"(d.w)
                 : "r"(a[0]), "r"(a[1]), "r"(a[2]), "r"(a[3]), "r"(b[0]), "r"(b[1]));
}

// ---------------- tf32 GEMM: C[M,N] = A[M,K] @ Bm[K,N] ----------------
// BM=128 BN=128 BK=32, 256 threads (8 warps, 4x2), warp tile 32x64.
#define GBM 128
#define GBN 128
#define GBK 32
#define BKP 36

__global__ __launch_bounds__(256, 1) void gemm_tf32(
    const float* __restrict__ A, int lda,
    const float* __restrict__ Bm, int ldb,
    float* __restrict__ C, int ldc,
    int M, int N, int K)
{
    __shared__ float As[GBM * BKP];
    __shared__ float Bt[GBN * BKP];   // transposed: Bt[n][k]

    int tid = threadIdx.x;
    int m0 = blockIdx.y * GBM, n0 = blockIdx.x * GBN;
    int warp = tid >> 5, lane = tid & 31;
    int wm = (warp & 3) * 32, wn = (warp >> 2) * 64;

    float4 acc[2][8];
#pragma unroll
    for (int i = 0; i < 2; i++)
#pragma unroll
        for (int j = 0; j < 8; j++) acc[i][j] = make_float4(0.f, 0.f, 0.f, 0.f);

    // A-ldmatrix per-lane geometry (matrix idx = lane>>3)
    int a_row = ((lane >> 3) & 1) * 8 + (lane & 7);   // + mt*16 + wm
    int a_col = ((lane >> 4) & 1) * 4;                // + kk
    uint32_t as_base = (uint32_t)__cvta_generic_to_shared(As);

    // B staging geometry: thread owns column n = tid&127, k-halves (tid>>7)*16
    int bn  = tid & 127;
    int bkg = (tid >> 7) * 16;
    bool nok = (n0 + bn) < N;

    float4 ar[4];
    float  br[4][4];

    int nk = K / GBK;

    // prologue: tile 0
#pragma unroll
    for (int it = 0; it < 4; it++) {
        int idx = tid + it * 256;
        int arow = idx >> 3, acq = (idx & 7) * 4;
        ar[it] = *(const float4*)&A[(size_t)(m0 + arow) * lda + acq];
    }
#pragma unroll
    for (int it = 0; it < 4; it++) {
        int kb = bkg + it * 4;
#pragma unroll
        for (int j = 0; j < 4; j++)
            br[it][j] = nok ? Bm[(size_t)(kb + j) * ldb + n0 + bn] : 0.f;
    }
#pragma unroll
    for (int it = 0; it < 4; it++) {
        int idx = tid + it * 256;
        int arow = idx >> 3, acq = (idx & 7) * 4;
        uint4 v = make_uint4(f2tf(ar[it].x), f2tf(ar[it].y), f2tf(ar[it].z), f2tf(ar[it].w));
        *(uint4*)&As[arow * BKP + acq] = v;
    }
#pragma unroll
    for (int it = 0; it < 4; it++) {
        uint4 v = make_uint4(f2tf(br[it][0]), f2tf(br[it][1]), f2tf(br[it][2]), f2tf(br[it][3]));
        *(uint4*)&Bt[bn * BKP + bkg + it * 4] = v;
    }
    __syncthreads();

    for (int t = 0; t < nk; t++) {
        // prefetch next tile into registers
        if (t + 1 < nk) {
            int k0 = (t + 1) * GBK;
#pragma unroll
            for (int it = 0; it < 4; it++) {
                int idx = tid + it * 256;
                int arow = idx >> 3, acq = (idx & 7) * 4;
                ar[it] = *(const float4*)&A[(size_t)(m0 + arow) * lda + k0 + acq];
            }
#pragma unroll
            for (int it = 0; it < 4; it++) {
                int kb = bkg + it * 4;
#pragma unroll
                for (int j = 0; j < 4; j++)
                    br[it][j] = nok ? Bm[(size_t)(k0 + kb + j) * ldb + n0 + bn] : 0.f;
            }
        }

        // compute: 4 k-steps of 8
#pragma unroll
        for (int ks = 0; ks < 4; ks++) {
            int kk = ks * 8;
            uint32_t afr[2][4];
#pragma unroll
            for (int mt = 0; mt < 2; mt++) {
                uint32_t addr = as_base +
                    ((wm + mt * 16 + a_row) * BKP + kk + a_col) * 4;
                ldsm4(afr[mt], addr);
            }
            uint32_t bfr[8][2];
#pragma unroll
            for (int nt = 0; nt < 8; nt++) {
                const float* p = &Bt[(wn + nt * 8 + (lane >> 2)) * BKP + kk + (lane & 3)];
                bfr[nt][0] = __float_as_uint(p[0]);
                bfr[nt][1] = __float_as_uint(p[4]);
            }
#pragma unroll
            for (int mt = 0; mt < 2; mt++)
#pragma unroll
                for (int nt = 0; nt < 8; nt++)
                    mma_tf32(acc[mt][nt], afr[mt], bfr[nt]);
        }
        __syncthreads();

        if (t + 1 < nk) {
#pragma unroll
            for (int it = 0; it < 4; it++) {
                int idx = tid + it * 256;
                int arow = idx >> 3, acq = (idx & 7) * 4;
                uint4 v = make_uint4(f2tf(ar[it].x), f2tf(ar[it].y), f2tf(ar[it].z), f2tf(ar[it].w));
                *(uint4*)&As[arow * BKP + acq] = v;
            }
#pragma unroll
            for (int it = 0; it < 4; it++) {
                uint4 v = make_uint4(f2tf(br[it][0]), f2tf(br[it][1]), f2tf(br[it][2]), f2tf(br[it][3]));
                *(uint4*)&Bt[bn * BKP + bkg + it * 4] = v;
            }
            __syncthreads();
        }
    }

    // epilogue
    int row_l = lane >> 2, col_l = (lane & 3) * 2;
#pragma unroll
    for (int mt = 0; mt < 2; mt++) {
#pragma unroll
        for (int nt = 0; nt < 8; nt++) {
            int r = m0 + wm + mt * 16 + row_l;
            int cc = n0 + wn + nt * 8 + col_l;
            if (cc < N) {
                *(float2*)&C[(size_t)r * ldc + cc] = make_float2(acc[mt][nt].x, acc[mt][nt].y);
                *(float2*)&C[(size_t)(r + 8) * ldc + cc] = make_float2(acc[mt][nt].z, acc[mt][nt].w);
            }
        }
    }
}

// ---------------- rmsnorm (in place), one block per row ----------------
__global__ __launch_bounds__(256) void rmsnorm_kernel(float* __restrict__ x, int stride, int D,
                                                      const float* __restrict__ w)
{
    int row = blockIdx.x;
    float* p = x + (size_t)row * stride;
    float ss = 0.f;
    for (int i = threadIdx.x; i < D; i += 256) { float v = p[i]; ss += v * v; }
    __shared__ float red[8];
#pragma unroll
    for (int off = 16; off; off >>= 1) ss += __shfl_down_sync(0xffffffffu, ss, off);
    if ((threadIdx.x & 31) == 0) red[threadIdx.x >> 5] = ss;
    __syncthreads();
    if (threadIdx.x == 0) {
        float t = 0.f;
#pragma unroll
        for (int i = 0; i < 8; i++) t += red[i];
        red[0] = rsqrtf(t / (float)D + 1e-6f);
    }
    __syncthreads();
    float inv = red[0];
    for (int i = threadIdx.x; i < D; i += 256) p[i] = p[i] * inv * w[i];
}

// ---------------- RoPE ----------------
__global__ void rope_q_kernel(float* __restrict__ q, const float* __restrict__ cosb,
                              const float* __restrict__ sinb)
{
    int idx = blockIdx.x * blockDim.x + threadIdx.x;
    if (idx >= MTOT * NH_ * 32) return;
    int j = idx & 31;
    int h = (idx >> 5) & (NH_ - 1);
    int m = idx >> 9;
    int s = m & (S_ - 1);
    float* base = q + (size_t)m * QW + h * DQK_ + DN_;
    float x = base[j], y = base[j + 32];
    float c0 = cosb[s * DR_ + j],      s0 = sinb[s * DR_ + j];
    float c1 = cosb[s * DR_ + j + 32], s1 = sinb[s * DR_ + j + 32];
    base[j]      = x * c0 - y * s0;
    base[j + 32] = y * c1 + x * s1;
}

__global__ void rope_k_kernel(float* __restrict__ ckv, const float* __restrict__ cosb,
                              const float* __restrict__ sinb)
{
    int idx = blockIdx.x * blockDim.x + threadIdx.x;
    if (idx >= MTOT * 32) return;
    int j = idx & 31;
    int m = idx >> 5;
    int s = m & (S_ - 1);
    float* base = ckv + (size_t)m * CKVW + KVLR_;
    float x = base[j], y = base[j + 32];
    float c0 = cosb[s * DR_ + j],      s0 = sinb[s * DR_ + j];
    float c1 = cosb[s * DR_ + j + 32], s1 = sinb[s * DR_ + j + 32];
    base[j]      = x * c0 - y * s0;
    base[j + 32] = y * c1 + x * s1;
}

// ---------------- flash attention (fp32 SIMT, unchanged) ----------------
#define QT_LD 68
#define V_LD  132
#define P_LD  68
#define ATTN_SMEM_FLOATS (192 * QT_LD * 2 + 64 * V_LD + 64 * P_LD + 192)
#define ATTN_SMEM_BYTES  (ATTN_SMEM_FLOATS * 4)

__global__ __launch_bounds__(256) void attn_kernel(
    const float* __restrict__ q, const float* __restrict__ kv,
    const float* __restrict__ ckv, float* __restrict__ ao)
{
    extern __shared__ float sm[];
    float* Qt   = sm;
    float* Kt   = Qt + 192 * QT_LD;
    float* Vs   = Kt + 192 * QT_LD;
    float* Pt   = Vs + 64 * V_LD;
    float* mrow = Pt + 64 * P_LD;
    float* lrow = mrow + 64;
    float* arow = lrow + 64;

    int qt = blockIdx.x, h = blockIdx.y, b = blockIdx.z;
    int tid = threadIdx.x, ty = tid >> 4, tx = tid & 15;
    int qr0 = ty * 4, kc0 = tx * 4, vd0 = tx * 8;

    for (int idx = tid; idx < 64 * 192; idx += 256) {
        int qr = idx / 192, d = idx - qr * 192;
        Qt[d * QT_LD + qr] =
            q[(size_t)(b * S_ + qt * 64 + qr) * QW + h * DQK_ + d] * SCALE_CONST;
    }
    if (tid < 64) { mrow[tid] = -1e30f; lrow[tid] = 0.f; }

    float o[4][8];
#pragma unroll
    for (int i = 0; i < 4; i++)
#pragma unroll
        for (int j = 0; j < 8; j++) o[i][j] = 0.f;

    __syncthreads();

    for (int kt = 0; kt <= qt; kt++) {
        int kbase = b * S_ + kt * 64;
        for (int idx = tid; idx < 64 * 192; idx += 256) {
            int kc = idx / 192, d = idx - kc * 192;
            float v = (d < 128)
                ? kv[(size_t)(kbase + kc) * KVW + h * 256 + d]
                : ckv[(size_t)(kbase + kc) * CKVW + KVLR_ + (d - 128)];
            Kt[d * QT_LD + kc] = v;
        }
        for (int idx = tid; idx < 64 * 128; idx += 256) {
            int kc = idx >> 7, d = idx & 127;
            Vs[kc * V_LD + d] = kv[(size_t)(kbase + kc) * KVW + h * 256 + 128 + d];
        }
        __syncthreads();

        float s4[4][4];
#pragma unroll
        for (int i = 0; i < 4; i++)
#pragma unroll
            for (int j = 0; j < 4; j++) s4[i][j] = 0.f;
#pragma unroll 4
        for (int d = 0; d < 192; d++) {
            float4 a = *(const float4*)&Qt[d * QT_LD + qr0];
            float4 bb = *(const float4*)&Kt[d * QT_LD + kc0];
            s4[0][0] += a.x * bb.x; s4[0][1] += a.x * bb.y; s4[0][2] += a.x * bb.z; s4[0][3] += a.x * bb.w;
            s4[1][0] += a.y * bb.x; s4[1][1] += a.y * bb.y; s4[1][2] += a.y * bb.z; s4[1][3] += a.y * bb.w;
            s4[2][0] += a.z * bb.x; s4[2][1] += a.z * bb.y; s4[2][2] += a.z * bb.z; s4[2][3] += a.z * bb.w;
            s4[3][0] += a.w * bb.x; s4[3][1] += a.w * bb.y; s4[3][2] += a.w * bb.z; s4[3][3] += a.w * bb.w;
        }
        if (kt == qt) {
#pragma unroll
            for (int i = 0; i < 4; i++)
#pragma unroll
                for (int j = 0; j < 4; j++)
                    if (kc0 + j > qr0 + i) s4[i][j] = -1e30f;
        }
#pragma unroll
        for (int i = 0; i < 4; i++)
#pragma unroll
            for (int j = 0; j < 4; j++)
                Pt[(kc0 + j) * P_LD + (qr0 + i)] = s4[i][j];
        __syncthreads();

        if (tid < 64) {
            int qr = tid;
            float mo = mrow[qr], rm = mo;
#pragma unroll 4
            for (int kc = 0; kc < 64; kc++) rm = fmaxf(rm, Pt[kc * P_LD + qr]);
            float sum = 0.f;
#pragma unroll 4
            for (int kc = 0; kc < 64; kc++) {
                float p = __expf(Pt[kc * P_LD + qr] - rm);
                Pt[kc * P_LD + qr] = p;
                sum += p;
            }
            float al = __expf(mo - rm);
            lrow[qr] = lrow[qr] * al + sum;
            mrow[qr] = rm;
            arow[qr] = al;
        }
        __syncthreads();

#pragma unroll
        for (int i = 0; i < 4; i++) {
            float al = arow[qr0 + i];
#pragma unroll
            for (int j = 0; j < 8; j++) o[i][j] *= al;
        }
#pragma unroll 2
        for (int kc = 0; kc < 64; kc++) {
            float4 p  = *(const float4*)&Pt[kc * P_LD + qr0];
            float4 v0 = *(const float4*)&Vs[kc * V_LD + vd0];
            float4 v1 = *(const float4*)&Vs[kc * V_LD + vd0 + 4];
            o[0][0] += p.x * v0.x; o[0][1] += p.x * v0.y; o[0][2] += p.x * v0.z; o[0][3] += p.x * v0.w;
            o[0][4] += p.x * v1.x; o[0][5] += p.x * v1.y; o[0][6] += p.x * v1.z; o[0][7] += p.x * v1.w;
            o[1][0] += p.y * v0.x; o[1][1] += p.y * v0.y; o[1][2] += p.y * v0.z; o[1][3] += p.y * v0.w;
            o[1][4] += p.y * v1.x; o[1][5] += p.y * v1.y; o[1][6] += p.y * v1.z; o[1][7] += p.y * v1.w;
            o[2][0] += p.z * v0.x; o[2][1] += p.z * v0.y; o[2][2] += p.z * v0.z; o[2][3] += p.z * v0.w;
            o[2][4] += p.z * v1.x; o[2][5] += p.z * v1.y; o[2][6] += p.z * v1.z; o[2][7] += p.z * v1.w;
            o[3][0] += p.w * v0.x; o[3][1] += p.w * v0.y; o[3][2] += p.w * v0.z; o[3][3] += p.w * v0.w;
            o[3][4] += p.w * v1.x; o[3][5] += p.w * v1.y; o[3][6] += p.w * v1.z; o[3][7] += p.w * v1.w;
        }
        __syncthreads();
    }

#pragma unroll
    for (int i = 0; i < 4; i++) {
        float inv = 1.f / lrow[qr0 + i];
        size_t row = (size_t)(b * S_ + qt * 64 + qr0 + i);
        float4 r0 = make_float4(o[i][0] * inv, o[i][1] * inv, o[i][2] * inv, o[i][3] * inv);
        float4 r1 = make_float4(o[i][4] * inv, o[i][5] * inv, o[i][6] * inv, o[i][7] * inv);
        *(float4*)&ao[row * AOW + h * DV_ + vd0]     = r0;
        *(float4*)&ao[row * AOW + h * DV_ + vd0 + 4] = r1;
    }
}

// ---------------- launch ----------------
extern "C" void kernel_launch(void* const* d_in, const int* in_sizes, int n_in,
                              void* d_out, int out_size)
{
    const float* hidden = (const float*)d_in[0];
    const float* cosb   = (const float*)d_in[2];
    const float* sinb   = (const float*)d_in[3];
    const float* w_qa   = (const float*)d_in[4];
    const float* qa_ln  = (const float*)d_in[5];
    const float* w_qb   = (const float*)d_in[6];
    const float* w_kva  = (const float*)d_in[7];
    const float* kva_ln = (const float*)d_in[8];
    const float* w_kvb  = (const float*)d_in[9];
    const float* w_o    = (const float*)d_in[10];
    float* out = (float*)d_out;

    float *qa, *ckv, *qbuf, *kvbuf, *ao;
    cudaGetSymbolAddress((void**)&qa,    g_qa);
    cudaGetSymbolAddress((void**)&ckv,   g_ckv);
    cudaGetSymbolAddress((void**)&qbuf,  g_q);
    cudaGetSymbolAddress((void**)&kvbuf, g_kv);
    cudaGetSymbolAddress((void**)&ao,    g_ao);

    cudaFuncSetAttribute(attn_kernel, cudaFuncAttributeMaxDynamicSharedMemorySize,
                         ATTN_SMEM_BYTES);

    // 1. q_a = hidden @ w_qa   (M=4096, N=1536, K=2048)
    gemm_tf32<<<dim3(QLR_ / 128, MTOT / 128), 256>>>(hidden, HID_, w_qa, QLR_, qa, QLR_,
                                                     MTOT, QLR_, HID_);
    // 2. ckv = hidden @ w_kva  (M=4096, N=576, K=2048)
    gemm_tf32<<<dim3((CKVW + 127) / 128, MTOT / 128), 256>>>(hidden, HID_, w_kva, CKVW,
                                                             ckv, CKVW, MTOT, CKVW, HID_);
    // 3. rmsnorms
    rmsnorm_kernel<<<MTOT, 256>>>(qa, QLR_, QLR_, qa_ln);
    rmsnorm_kernel<<<MTOT, 256>>>(ckv, CKVW, KVLR_, kva_ln);
    // 4. q = qa_norm @ w_qb    (M=4096, N=3072, K=1536)
    gemm_tf32<<<dim3(QW / 128, MTOT / 128), 256>>>(qa, QLR_, w_qb, QW, qbuf, QW,
                                                   MTOT, QW, QLR_);
    // 5. kv = ckv_norm @ w_kvb (M=4096, N=4096, K=512)
    gemm_tf32<<<dim3(KVW / 128, MTOT / 128), 256>>>(ckv, CKVW, w_kvb, KVW, kvbuf, KVW,
                                                    MTOT, KVW, KVLR_);
    // 6. RoPE
    rope_q_kernel<<<(MTOT * NH_ * 32 + 255) / 256, 256>>>(qbuf, cosb, sinb);
    rope_k_kernel<<<(MTOT * 32 + 255) / 256, 256>>>(ckv, cosb, sinb);
    // 7. attention
    attn_kernel<<<dim3(S_ / 64, NH_, B_), 256, ATTN_SMEM_BYTES>>>(qbuf, kvbuf, ckv, ao);
    // 8. out = ao @ w_o        (M=4096, N=2048, K=2048)
    gemm_tf32<<<dim3(HID_ / 128, MTOT / 128), 256>>>(ao, AOW, w_o, HID_, out, HID_,
                                                     MTOT, HID_, AOW);
}

// round 3
// speedup vs baseline: 1.7928x; 1.1935x over previous
#include <cuda_runtime.h>
#include <math.h>
#include <stdint.h>

#define B_    2
#define S_    2048
#define HID_  2048
#define NH_   16
#define QLR_  1536
#define KVLR_ 512
#define DN_   128
#define DR_   64
#define DV_   128
#define DQK_  192
#define MTOT  (B_ * S_)            // 4096
#define CKVW  (KVLR_ + DR_)        // 576
#define QW    (NH_ * DQK_)         // 3072
#define KVW   (NH_ * (DN_ + DV_))  // 4096
#define AOW   (NH_ * DV_)          // 2048
#define SCALE_CONST 0.07216878364870322f   // 192^-0.5

// ---------------- scratch (no allocation allowed) ----------------
__device__ float g_qa [(size_t)MTOT * QLR_];
__device__ float g_ckv[(size_t)MTOT * CKVW];
__device__ float g_q  [(size_t)MTOT * QW];
__device__ float g_kv [(size_t)MTOT * KVW];
__device__ float g_ao [(size_t)MTOT * AOW];
__device__ float g_vt [(size_t)B_ * NH_ * DV_ * S_];   // V transposed: [b][h][vd][s]

// ---------------- tf32 mma helpers ----------------
__device__ __forceinline__ uint32_t f2tf(float f) {
    uint32_t u;
    asm("cvt.rna.tf32.f32 %0, %1;" : "=r"(u) : "f"(f));
    return u;
}

__device__ __forceinline__ void ldsm4(uint32_t* r, uint32_t addr) {
    asm volatile("ldmatrix.sync.aligned.m8n8.x4.shared.b16 {%0,%1,%2,%3},[%4];"
                 : "=r"(r[0]), "=r"(r[1]), "=r"(r[2]), "=r"(r[3]) : "r"(addr));
}

__device__ __forceinline__ void mma_tf32(float4& d, const uint32_t* a, uint32_t b0, uint32_t b1) {
    asm volatile("mma.sync.aligned.m16n8k8.row.col.f32.tf32.tf32.f32 "
                 "{%0,%1,%2,%3},{%4,%5,%6,%7},{%8,%9},{%0,%1,%2,%3};"
                 : "+f"(d.x), "+f"(d.y), "+f"(d.z), "+f"(d.w)
                 : "r"(a[0]), "r"(a[1]), "r"(a[2]), "r"(a[3]), "r"(b0), "r"(b1));
}

// ---------------- tf32 GEMM: C[M,N] = A[M,K] @ Bm[K,N] ----------------
#define GBM 128
#define GBN 128
#define GBK 32
#define BKP 36

__global__ __launch_bounds__(256, 1) void gemm_tf32(
    const float* __restrict__ A, int lda,
    const float* __restrict__ Bm, int ldb,
    float* __restrict__ C, int ldc,
    int M, int N, int K,
    float* __restrict__ vtp)   // non-null: kvb mode, V half scattered transposed
{
    __shared__ float As[GBM * BKP];
    __shared__ float Bt[GBN * BKP];

    int tid = threadIdx.x;
    int m0 = blockIdx.y * GBM, n0 = blockIdx.x * GBN;
    int warp = tid >> 5, lane = tid & 31;
    int wm = (warp & 3) * 32, wn = (warp >> 2) * 64;

    float4 acc[2][8];
#pragma unroll
    for (int i = 0; i < 2; i++)
#pragma unroll
        for (int j = 0; j < 8; j++) acc[i][j] = make_float4(0.f, 0.f, 0.f, 0.f);

    int a_row = ((lane >> 3) & 1) * 8 + (lane & 7);
    int a_col = ((lane >> 4) & 1) * 4;
    uint32_t as_base = (uint32_t)__cvta_generic_to_shared(As);

    int bn  = tid & 127;
    int bkg = (tid >> 7) * 16;
    bool nok = (n0 + bn) < N;

    float4 ar[4];
    float  br[4][4];
    int nk = K / GBK;

#pragma unroll
    for (int it = 0; it < 4; it++) {
        int idx = tid + it * 256;
        int arow = idx >> 3, acq = (idx & 7) * 4;
        ar[it] = *(const float4*)&A[(size_t)(m0 + arow) * lda + acq];
    }
#pragma unroll
    for (int it = 0; it < 4; it++) {
        int kb = bkg + it * 4;
#pragma unroll
        for (int j = 0; j < 4; j++)
            br[it][j] = nok ? Bm[(size_t)(kb + j) * ldb + n0 + bn] : 0.f;
    }
#pragma unroll
    for (int it = 0; it < 4; it++) {
        int idx = tid + it * 256;
        int arow = idx >> 3, acq = (idx & 7) * 4;
        uint4 v = make_uint4(f2tf(ar[it].x), f2tf(ar[it].y), f2tf(ar[it].z), f2tf(ar[it].w));
        *(uint4*)&As[arow * BKP + acq] = v;
    }
#pragma unroll
    for (int it = 0; it < 4; it++) {
        uint4 v = make_uint4(f2tf(br[it][0]), f2tf(br[it][1]), f2tf(br[it][2]), f2tf(br[it][3]));
        *(uint4*)&Bt[bn * BKP + bkg + it * 4] = v;
    }
    __syncthreads();

    for (int t = 0; t < nk; t++) {
        if (t + 1 < nk) {
            int k0 = (t + 1) * GBK;
#pragma unroll
            for (int it = 0; it < 4; it++) {
                int idx = tid + it * 256;
                int arow = idx >> 3, acq = (idx & 7) * 4;
                ar[it] = *(const float4*)&A[(size_t)(m0 + arow) * lda + k0 + acq];
            }
#pragma unroll
            for (int it = 0; it < 4; it++) {
                int kb = bkg + it * 4;
#pragma unroll
                for (int j = 0; j < 4; j++)
                    br[it][j] = nok ? Bm[(size_t)(k0 + kb + j) * ldb + n0 + bn] : 0.f;
            }
        }

#pragma unroll
        for (int ks = 0; ks < 4; ks++) {
            int kk = ks * 8;
            uint32_t afr[2][4];
#pragma unroll
            for (int mt = 0; mt < 2; mt++) {
                uint32_t addr = as_base + ((wm + mt * 16 + a_row) * BKP + kk + a_col) * 4;
                ldsm4(afr[mt], addr);
            }
            uint32_t bfr[8][2];
#pragma unroll
            for (int nt = 0; nt < 8; nt++) {
                const float* p = &Bt[(wn + nt * 8 + (lane >> 2)) * BKP + kk + (lane & 3)];
                bfr[nt][0] = __float_as_uint(p[0]);
                bfr[nt][1] = __float_as_uint(p[4]);
            }
#pragma unroll
            for (int mt = 0; mt < 2; mt++)
#pragma unroll
                for (int nt = 0; nt < 8; nt++)
                    mma_tf32(acc[mt][nt], afr[mt], bfr[nt][0], bfr[nt][1]);
        }
        __syncthreads();

        if (t + 1 < nk) {
#pragma unroll
            for (int it = 0; it < 4; it++) {
                int idx = tid + it * 256;
                int arow = idx >> 3, acq = (idx & 7) * 4;
                uint4 v = make_uint4(f2tf(ar[it].x), f2tf(ar[it].y), f2tf(ar[it].z), f2tf(ar[it].w));
                *(uint4*)&As[arow * BKP + acq] = v;
            }
#pragma unroll
            for (int it = 0; it < 4; it++) {
                uint4 v = make_uint4(f2tf(br[it][0]), f2tf(br[it][1]), f2tf(br[it][2]), f2tf(br[it][3]));
                *(uint4*)&Bt[bn * BKP + bkg + it * 4] = v;
            }
            __syncthreads();
        }
    }

    int row_l = lane >> 2, col_l = (lane & 3) * 2;
#pragma unroll
    for (int mt = 0; mt < 2; mt++) {
#pragma unroll
        for (int nt = 0; nt < 8; nt++) {
            int r = m0 + wm + mt * 16 + row_l;
            int cc = n0 + wn + nt * 8 + col_l;
            if (cc >= N) continue;
            float4 a = acc[mt][nt];
            if (vtp != nullptr && (cc & 255) >= 128) {
                // V half: scatter transposed into vt[b][h][vd][s]
                int hh = cc >> 8, vd = (cc & 255) - 128;
                int bb = r >> 11, ss = r & 2047;
                size_t base = ((size_t)(bb * NH_ + hh) * DV_ + vd) * (size_t)S_;
                vtp[base + ss]            = a.x;
                vtp[base + S_ + ss]       = a.y;   // vd+1
                vtp[base + ss + 8]        = a.z;   // row r+8
                vtp[base + S_ + ss + 8]   = a.w;
            } else {
                *(float2*)&C[(size_t)r * ldc + cc]       = make_float2(a.x, a.y);
                *(float2*)&C[(size_t)(r + 8) * ldc + cc] = make_float2(a.z, a.w);
            }
        }
    }
}

// ---------------- rmsnorm (in place) ----------------
__global__ __launch_bounds__(256) void rmsnorm_kernel(float* __restrict__ x, int stride, int D,
                                                      const float* __restrict__ w)
{
    int row = blockIdx.x;
    float* p = x + (size_t)row * stride;
    float ss = 0.f;
    for (int i = threadIdx.x; i < D; i += 256) { float v = p[i]; ss += v * v; }
    __shared__ float red[8];
#pragma unroll
    for (int off = 16; off; off >>= 1) ss += __shfl_down_sync(0xffffffffu, ss, off);
    if ((threadIdx.x & 31) == 0) red[threadIdx.x >> 5] = ss;
    __syncthreads();
    if (threadIdx.x == 0) {
        float t = 0.f;
#pragma unroll
        for (int i = 0; i < 8; i++) t += red[i];
        red[0] = rsqrtf(t / (float)D + 1e-6f);
    }
    __syncthreads();
    float inv = red[0];
    for (int i = threadIdx.x; i < D; i += 256) p[i] = p[i] * inv * w[i];
}

// ---------------- RoPE ----------------
__global__ void rope_q_kernel(float* __restrict__ q, const float* __restrict__ cosb,
                              const float* __restrict__ sinb)
{
    int idx = blockIdx.x * blockDim.x + threadIdx.x;
    if (idx >= MTOT * NH_ * 32) return;
    int j = idx & 31;
    int h = (idx >> 5) & (NH_ - 1);
    int m = idx >> 9;
    int s = m & (S_ - 1);
    float* base = q + (size_t)m * QW + h * DQK_ + DN_;
    float x = base[j], y = base[j + 32];
    float c0 = cosb[s * DR_ + j],      s0 = sinb[s * DR_ + j];
    float c1 = cosb[s * DR_ + j + 32], s1 = sinb[s * DR_ + j + 32];
    base[j]      = x * c0 - y * s0;
    base[j + 32] = y * c1 + x * s1;
}

__global__ void rope_k_kernel(float* __restrict__ ckv, const float* __restrict__ cosb,
                              const float* __restrict__ sinb)
{
    int idx = blockIdx.x * blockDim.x + threadIdx.x;
    if (idx >= MTOT * 32) return;
    int j = idx & 31;
    int m = idx >> 5;
    int s = m & (S_ - 1);
    float* base = ckv + (size_t)m * CKVW + KVLR_;
    float x = base[j], y = base[j + 32];
    float c0 = cosb[s * DR_ + j],      s0 = sinb[s * DR_ + j];
    float c1 = cosb[s * DR_ + j + 32], s1 = sinb[s * DR_ + j + 32];
    base[j]      = x * c0 - y * s0;
    base[j + 32] = y * c1 + x * s1;
}

// ---------------- tensor-core flash attention ----------------
// grid (32, NH, B); 256 threads = 8 warps: 4 q-stripes (16 rows) x 2 kc-halves (32).
#define AQ_LD 196
#define AK_LD 196
#define AV_LD 68
#define AP_LD 68
#define AO_LD 132
#define ATTN_SMEM_FLOATS (64*AQ_LD + 64*AK_LD + 128*AV_LD + 64*AP_LD + 256)
#define ATTN_SMEM_BYTES  (ATTN_SMEM_FLOATS * 4)

__global__ __launch_bounds__(256, 1) void attn_mma(
    const float* __restrict__ q, const float* __restrict__ kv,
    const float* __restrict__ ckv, const float* __restrict__ vt,
    float* __restrict__ ao)
{
    extern __shared__ float sm[];
    float* Qs   = sm;                     // [64][196] tf32
    float* Kt   = Qs + 64 * AQ_LD;        // [64][196] tf32
    float* Vt   = Kt + 64 * AK_LD;        // [128][68] tf32 (V transposed: [vd][kc])
    float* Ps   = Vt + 128 * AV_LD;       // [64][68]  tf32
    float* mbuf = Ps + 64 * AP_LD;        // [2][64]
    float* lbuf = mbuf + 128;             // [2][64]

    int qt = blockIdx.x, h = blockIdx.y, b = blockIdx.z;
    int tid = threadIdx.x, warp = tid >> 5, lane = tid & 31;
    int qs = (warp & 3) * 16;     // warp's q-stripe base (within 64)
    int kh = warp >> 2;           // kc half: 0 or 1 (cols kh*32..+31)
    int r  = lane >> 2, qd = lane & 3;

    int a_row = ((lane >> 3) & 1) * 8 + (lane & 7);
    int a_col = ((lane >> 4) & 1) * 4;
    uint32_t smem_base = (uint32_t)__cvta_generic_to_shared(sm);
    uint32_t ps_off = (uint32_t)((Ps - sm)) * 4;

    int qbase = b * S_ + qt * 64;

    // stage Q (scaled, tf32)
    for (int i = tid; i < 64 * 48; i += 256) {
        int qr = i / 48, dq = (i - qr * 48) * 4;
        float4 v = *(const float4*)&q[(size_t)(qbase + qr) * QW + h * DQK_ + dq];
        uint4 u = make_uint4(f2tf(v.x * SCALE_CONST), f2tf(v.y * SCALE_CONST),
                             f2tf(v.z * SCALE_CONST), f2tf(v.w * SCALE_CONST));
        *(uint4*)&Qs[qr * AQ_LD + dq] = u;
    }

    float4 o[16];
#pragma unroll
    for (int i = 0; i < 16; i++) o[i] = make_float4(0.f, 0.f, 0.f, 0.f);
    float m_r = -1e30f, m_r8 = -1e30f, l_r = 0.f, l_r8 = 0.f;

    const float* vtp = &vt[(size_t)(b * NH_ + h) * DV_ * S_];

    for (int kt = 0; kt <= qt; kt++) {
        __syncthreads();
        int kbase = b * S_ + kt * 64;
        // stage K (k_nope from kv, k_pe from roped ckv), tf32
        for (int i = tid; i < 64 * 48; i += 256) {
            int kc = i / 48, dq = (i - kc * 48) * 4;
            float4 v;
            if (dq < 128) v = *(const float4*)&kv[(size_t)(kbase + kc) * KVW + h * 256 + dq];
            else          v = *(const float4*)&ckv[(size_t)(kbase + kc) * CKVW + KVLR_ + dq - 128];
            uint4 u = make_uint4(f2tf(v.x), f2tf(v.y), f2tf(v.z), f2tf(v.w));
            *(uint4*)&Kt[kc * AK_LD + dq] = u;
        }
        // stage Vt (coalesced rows from transposed global), tf32
        for (int i = tid; i < 128 * 16; i += 256) {
            int vd = i >> 4, kq = (i & 15) * 4;
            float4 v = *(const float4*)&vtp[(size_t)vd * S_ + kt * 64 + kq];
            uint4 u = make_uint4(f2tf(v.x), f2tf(v.y), f2tf(v.z), f2tf(v.w));
            *(uint4*)&Vt[vd * AV_LD + kq] = u;
        }
        __syncthreads();

        // S = Q @ K^T  (warp: 16 rows x 32 cols of its half)
        float4 s4[4];
#pragma unroll
        for (int nt = 0; nt < 4; nt++) s4[nt] = make_float4(0.f, 0.f, 0.f, 0.f);
#pragma unroll
        for (int ks = 0; ks < 24; ks++) {
            uint32_t af[4];
            ldsm4(af, smem_base + ((qs + a_row) * AQ_LD + ks * 8 + a_col) * 4);
#pragma unroll
            for (int nt = 0; nt < 4; nt++) {
                const float* p = &Kt[(kh * 32 + nt * 8 + r) * AK_LD + ks * 8 + qd];
                mma_tf32(s4[nt], af, __float_as_uint(p[0]), __float_as_uint(p[4]));
            }
        }

        // causal mask (tile-aligned: only on diagonal tile)
        if (kt == qt) {
#pragma unroll
            for (int nt = 0; nt < 4; nt++) {
                int c0 = kh * 32 + nt * 8 + 2 * qd;
                int row = qs + r;
                if (c0     > row)     s4[nt].x = -1e30f;
                if (c0 + 1 > row)     s4[nt].y = -1e30f;
                if (c0     > row + 8) s4[nt].z = -1e30f;
                if (c0 + 1 > row + 8) s4[nt].w = -1e30f;
            }
        }

        // local row max + quad reduce
        float lm_r = -1e30f, lm_r8 = -1e30f;
#pragma unroll
        for (int nt = 0; nt < 4; nt++) {
            lm_r  = fmaxf(lm_r,  fmaxf(s4[nt].x, s4[nt].y));
            lm_r8 = fmaxf(lm_r8, fmaxf(s4[nt].z, s4[nt].w));
        }
        lm_r  = fmaxf(lm_r,  __shfl_xor_sync(0xffffffffu, lm_r, 1));
        lm_r  = fmaxf(lm_r,  __shfl_xor_sync(0xffffffffu, lm_r, 2));
        lm_r8 = fmaxf(lm_r8, __shfl_xor_sync(0xffffffffu, lm_r8, 1));
        lm_r8 = fmaxf(lm_r8, __shfl_xor_sync(0xffffffffu, lm_r8, 2));
        if (qd == 0) {
            mbuf[kh * 64 + qs + r]     = lm_r;
            mbuf[kh * 64 + qs + r + 8] = lm_r8;
        }
        __syncthreads();
        float mn_r  = fmaxf(m_r,  fmaxf(mbuf[qs + r],     mbuf[64 + qs + r]));
        float mn_r8 = fmaxf(m_r8, fmaxf(mbuf[qs + r + 8], mbuf[64 + qs + r + 8]));
        float al_r  = __expf(m_r - mn_r);
        float al_r8 = __expf(m_r8 - mn_r8);
        m_r = mn_r; m_r8 = mn_r8;

        // p = exp(s - m), store tf32 to Ps, accumulate row sums
        float ps_r = 0.f, ps_r8 = 0.f;
#pragma unroll
        for (int nt = 0; nt < 4; nt++) {
            float px = __expf(s4[nt].x - mn_r);
            float py = __expf(s4[nt].y - mn_r);
            float pz = __expf(s4[nt].z - mn_r8);
            float pw = __expf(s4[nt].w - mn_r8);
            ps_r  += px + py;
            ps_r8 += pz + pw;
            int col = kh * 32 + nt * 8 + 2 * qd;
            *(uint2*)&Ps[(qs + r) * AP_LD + col]     = make_uint2(f2tf(px), f2tf(py));
            *(uint2*)&Ps[(qs + r + 8) * AP_LD + col] = make_uint2(f2tf(pz), f2tf(pw));
        }
        ps_r  += __shfl_xor_sync(0xffffffffu, ps_r, 1);
        ps_r  += __shfl_xor_sync(0xffffffffu, ps_r, 2);
        ps_r8 += __shfl_xor_sync(0xffffffffu, ps_r8, 1);
        ps_r8 += __shfl_xor_sync(0xffffffffu, ps_r8, 2);
        l_r  = l_r  * al_r  + ps_r;
        l_r8 = l_r8 * al_r8 + ps_r8;
        __syncwarp();

        // rescale O, then O += P @ V  (V from transposed tile)
#pragma unroll
        for (int nt = 0; nt < 16; nt++) {
            o[nt].x *= al_r;  o[nt].y *= al_r;
            o[nt].z *= al_r8; o[nt].w *= al_r8;
        }
#pragma unroll
        for (int ks = 0; ks < 4; ks++) {
            uint32_t af[4];
            ldsm4(af, smem_base + ps_off + ((qs + a_row) * AP_LD + kh * 32 + ks * 8 + a_col) * 4);
#pragma unroll
            for (int nt = 0; nt < 16; nt++) {
                const float* p = &Vt[(nt * 8 + r) * AV_LD + kh * 32 + ks * 8 + qd];
                mma_tf32(o[nt], af, __float_as_uint(p[0]), __float_as_uint(p[4]));
            }
        }
    }

    // combine the two kc-halves
    __syncthreads();
    float* obuf = Kt;   // reuse [64][132]
    if (qd == 0) {
        lbuf[kh * 64 + qs + r]     = l_r;
        lbuf[kh * 64 + qs + r + 8] = l_r8;
    }
    if (kh == 1) {
#pragma unroll
        for (int nt = 0; nt < 16; nt++) {
            int col = nt * 8 + 2 * qd;
            *(float2*)&obuf[(qs + r) * AO_LD + col]     = make_float2(o[nt].x, o[nt].y);
            *(float2*)&obuf[(qs + r + 8) * AO_LD + col] = make_float2(o[nt].z, o[nt].w);
        }
    }
    __syncthreads();
    if (kh == 0) {
        float inv_r  = 1.f / (lbuf[qs + r]     + lbuf[64 + qs + r]);
        float inv_r8 = 1.f / (lbuf[qs + r + 8] + lbuf[64 + qs + r + 8]);
#pragma unroll
        for (int nt = 0; nt < 16; nt++) {
            int col = nt * 8 + 2 * qd;
            float2 p0 = *(float2*)&obuf[(qs + r) * AO_LD + col];
            float2 p1 = *(float2*)&obuf[(qs + r + 8) * AO_LD + col];
            size_t row0 = (size_t)(qbase + qs + r);
            *(float2*)&ao[row0 * AOW + h * DV_ + col] =
                make_float2((o[nt].x + p0.x) * inv_r, (o[nt].y + p0.y) * inv_r);
            *(float2*)&ao[(row0 + 8) * AOW + h * DV_ + col] =
                make_float2((o[nt].z + p1.x) * inv_r8, (o[nt].w + p1.y) * inv_r8);
        }
    }
}

// ---------------- launch ----------------
extern "C" void kernel_launch(void* const* d_in, const int* in_sizes, int n_in,
                              void* d_out, int out_size)
{
    const float* hidden = (const float*)d_in[0];
    const float* cosb   = (const float*)d_in[2];
    const float* sinb   = (const float*)d_in[3];
    const float* w_qa   = (const float*)d_in[4];
    const float* qa_ln  = (const float*)d_in[5];
    const float* w_qb   = (const float*)d_in[6];
    const float* w_kva  = (const float*)d_in[7];
    const float* kva_ln = (const float*)d_in[8];
    const float* w_kvb  = (const float*)d_in[9];
    const float* w_o    = (const float*)d_in[10];
    float* out = (float*)d_out;

    float *qa, *ckv, *qbuf, *kvbuf, *ao, *vt;
    cudaGetSymbolAddress((void**)&qa,    g_qa);
    cudaGetSymbolAddress((void**)&ckv,   g_ckv);
    cudaGetSymbolAddress((void**)&qbuf,  g_q);
    cudaGetSymbolAddress((void**)&kvbuf, g_kv);
    cudaGetSymbolAddress((void**)&ao,    g_ao);
    cudaGetSymbolAddress((void**)&vt,    g_vt);

    cudaFuncSetAttribute(attn_mma, cudaFuncAttributeMaxDynamicSharedMemorySize,
                         ATTN_SMEM_BYTES);

    // 1. q_a = hidden @ w_qa
    gemm_tf32<<<dim3(QLR_ / 128, MTOT / 128), 256>>>(hidden, HID_, w_qa, QLR_, qa, QLR_,
                                                     MTOT, QLR_, HID_, nullptr);
    // 2. ckv = hidden @ w_kva
    gemm_tf32<<<dim3((CKVW + 127) / 128, MTOT / 128), 256>>>(hidden, HID_, w_kva, CKVW,
                                                             ckv, CKVW, MTOT, CKVW, HID_, nullptr);
    // 3. rmsnorms
    rmsnorm_kernel<<<MTOT, 256>>>(qa, QLR_, QLR_, qa_ln);
    rmsnorm_kernel<<<MTOT, 256>>>(ckv, CKVW, KVLR_, kva_ln);
    // 4. q = qa_norm @ w_qb
    gemm_tf32<<<dim3(QW / 128, MTOT / 128), 256>>>(qa, QLR_, w_qb, QW, qbuf, QW,
                                                   MTOT, QW, QLR_, nullptr);
    // 5. kv = ckv_norm @ w_kvb  (V half scattered transposed into vt)
    gemm_tf32<<<dim3(KVW / 128, MTOT / 128), 256>>>(ckv, CKVW, w_kvb, KVW, kvbuf, KVW,
                                                    MTOT, KVW, KVLR_, vt);
    // 6. RoPE
    rope_q_kernel<<<(MTOT * NH_ * 32 + 255) / 256, 256>>>(qbuf, cosb, sinb);
    rope_k_kernel<<<(MTOT * 32 + 255) / 256, 256>>>(ckv, cosb, sinb);
    // 7. attention (tensor core)
    attn_mma<<<dim3(S_ / 64, NH_, B_), 256, ATTN_SMEM_BYTES>>>(qbuf, kvbuf, ckv, vt, ao);
    // 8. out = ao @ w_o
    gemm_tf32<<<dim3(HID_ / 128, MTOT / 128), 256>>>(ao, AOW, w_o, HID_, out, HID_,
                                                     MTOT, HID_, AOW, nullptr);
}

// round 4
// speedup vs baseline: 3.3000x; 1.8407x over previous
#include <cuda_runtime.h>
#include <math.h>
#include <stdint.h>

#define B_    2
#define S_    2048
#define HID_  2048
#define NH_   16
#define QLR_  1536
#define KVLR_ 512
#define DN_   128
#define DR_   64
#define DV_   128
#define DQK_  192
#define MTOT  (B_ * S_)            // 4096
#define CKVW  (KVLR_ + DR_)        // 576
#define QW    (NH_ * DQK_)         // 3072
#define KVW   (NH_ * (DN_ + DV_))  // 4096
#define AOW   (NH_ * DV_)          // 2048
#define SCALE_CONST 0.07216878364870322f   // 192^-0.5

// ---------------- scratch (no allocation allowed) ----------------
__device__ float g_qa [(size_t)MTOT * QLR_];
__device__ float g_ckv[(size_t)MTOT * CKVW];
__device__ float g_q  [(size_t)MTOT * QW];
__device__ float g_kv [(size_t)MTOT * KVW];
__device__ float g_ao [(size_t)MTOT * AOW];
__device__ float g_vt [(size_t)B_ * NH_ * DV_ * S_];   // V transposed: [b][h][vd][s]

// ---------------- tf32 mma helpers ----------------
__device__ __forceinline__ uint32_t f2tf(float f) {
    uint32_t u;
    asm("cvt.rna.tf32.f32 %0, %1;" : "=r"(u) : "f"(f));
    return u;
}

__device__ __forceinline__ void ldsm4(uint32_t* r, uint32_t addr) {
    asm volatile("ldmatrix.sync.aligned.m8n8.x4.shared.b16 {%0,%1,%2,%3},[%4];"
                 : "=r"(r[0]), "=r"(r[1]), "=r"(r[2]), "=r"(r[3]) : "r"(addr));
}

__device__ __forceinline__ void mma_tf32(float4& d, const uint32_t* a, uint32_t b0, uint32_t b1) {
    asm volatile("mma.sync.aligned.m16n8k8.row.col.f32.tf32.tf32.f32 "
                 "{%0,%1,%2,%3},{%4,%5,%6,%7},{%8,%9},{%0,%1,%2,%3};"
                 : "+f"(d.x), "+f"(d.y), "+f"(d.z), "+f"(d.w)
                 : "r"(a[0]), "r"(a[1]), "r"(a[2]), "r"(a[3]), "r"(b0), "r"(b1));
}

// ---------------- tf32 GEMM: C[M,N] = A[M,K] @ Bm[K,N] ----------------
// BM=128 BN=128 BK=32, 256 threads (8 warps = 2m x 4n), warp tile 64x32.
// B staged UNtransposed [k][n] (float4 LDG + float4 STS); b-frags via 2 scalar
// LDS each, provably conflict-free with BLD=132.
#define GBM 128
#define GBN 128
#define GBK 32
#define ALD 36
#define BLD 132

__global__ __launch_bounds__(256, 1) void gemm_tf32(
    const float* __restrict__ A, int lda,
    const float* __restrict__ Bm, int ldb,
    float* __restrict__ C, int ldc,
    int M, int N, int K,
    float* __restrict__ vtp)   // non-null: kvb mode, V half scattered transposed
{
    __shared__ float As[GBM * ALD];
    __shared__ float Bs[GBK * BLD];

    int tid = threadIdx.x;
    int m0 = blockIdx.y * GBM, n0 = blockIdx.x * GBN;
    int warp = tid >> 5, lane = tid & 31;
    int wm = (warp & 1) * 64, wn = (warp >> 1) * 32;
    int r = lane >> 2, qd = lane & 3;

    float4 acc[4][4];
#pragma unroll
    for (int i = 0; i < 4; i++)
#pragma unroll
        for (int j = 0; j < 4; j++) acc[i][j] = make_float4(0.f, 0.f, 0.f, 0.f);

    int a_row = ((lane >> 3) & 1) * 8 + (lane & 7);
    int a_col = ((lane >> 4) & 1) * 4;
    uint32_t as_base = (uint32_t)__cvta_generic_to_shared(As);

    // staging geometry
    // A: chunk c = tid + it*256 : arow = c>>3, akc = (c&7)*4
    // B: chunk c = tid + it*256 : krow = c>>5, bnc = (c&31)*4
    int bnc = (lane & 31) * 4;       // (tid&31)*4
    int s_arow = tid >> 3, s_akc = (tid & 7) * 4;
    int s_krow = tid >> 5;
    bool nok = (n0 + bnc) < N;       // N % 4 == 0 -> full float4 in bounds

    float4 ar[4], br[4];
    int nk = K / GBK;

    // prologue: tile 0
#pragma unroll
    for (int it = 0; it < 4; it++)
        ar[it] = *(const float4*)&A[(size_t)(m0 + s_arow + it * 32) * lda + s_akc];
#pragma unroll
    for (int it = 0; it < 4; it++)
        br[it] = nok ? *(const float4*)&Bm[(size_t)(s_krow + it * 8) * ldb + n0 + bnc]
                     : make_float4(0.f, 0.f, 0.f, 0.f);
#pragma unroll
    for (int it = 0; it < 4; it++) {
        uint4 v = make_uint4(f2tf(ar[it].x), f2tf(ar[it].y), f2tf(ar[it].z), f2tf(ar[it].w));
        *(uint4*)&As[(s_arow + it * 32) * ALD + s_akc] = v;
    }
#pragma unroll
    for (int it = 0; it < 4; it++) {
        uint4 v = make_uint4(f2tf(br[it].x), f2tf(br[it].y), f2tf(br[it].z), f2tf(br[it].w));
        *(uint4*)&Bs[(s_krow + it * 8) * BLD + bnc] = v;
    }
    __syncthreads();

    for (int t = 0; t < nk; t++) {
        if (t + 1 < nk) {
            int k0 = (t + 1) * GBK;
#pragma unroll
            for (int it = 0; it < 4; it++)
                ar[it] = *(const float4*)&A[(size_t)(m0 + s_arow + it * 32) * lda + k0 + s_akc];
#pragma unroll
            for (int it = 0; it < 4; it++)
                br[it] = nok ? *(const float4*)&Bm[(size_t)(k0 + s_krow + it * 8) * ldb + n0 + bnc]
                             : make_float4(0.f, 0.f, 0.f, 0.f);
        }

#pragma unroll
        for (int ks = 0; ks < 4; ks++) {
            int kk = ks * 8;
            uint32_t af[4][4];
#pragma unroll
            for (int mt = 0; mt < 4; mt++) {
                uint32_t addr = as_base + ((wm + mt * 16 + a_row) * ALD + kk + a_col) * 4;
                ldsm4(af[mt], addr);
            }
            uint32_t b0[4], b1[4];
#pragma unroll
            for (int nt = 0; nt < 4; nt++) {
                const float* p = &Bs[(kk + qd) * BLD + wn + nt * 8 + r];
                b0[nt] = __float_as_uint(p[0]);
                b1[nt] = __float_as_uint(p[4 * BLD]);
            }
#pragma unroll
            for (int mt = 0; mt < 4; mt++)
#pragma unroll
                for (int nt = 0; nt < 4; nt++)
                    mma_tf32(acc[mt][nt], af[mt], b0[nt], b1[nt]);
        }
        __syncthreads();

        if (t + 1 < nk) {
#pragma unroll
            for (int it = 0; it < 4; it++) {
                uint4 v = make_uint4(f2tf(ar[it].x), f2tf(ar[it].y), f2tf(ar[it].z), f2tf(ar[it].w));
                *(uint4*)&As[(s_arow + it * 32) * ALD + s_akc] = v;
            }
#pragma unroll
            for (int it = 0; it < 4; it++) {
                uint4 v = make_uint4(f2tf(br[it].x), f2tf(br[it].y), f2tf(br[it].z), f2tf(br[it].w));
                *(uint4*)&Bs[(s_krow + it * 8) * BLD + bnc] = v;
            }
            __syncthreads();
        }
    }

    int row_l = lane >> 2, col_l = (lane & 3) * 2;
#pragma unroll
    for (int mt = 0; mt < 4; mt++) {
#pragma unroll
        for (int nt = 0; nt < 4; nt++) {
            int rr = m0 + wm + mt * 16 + row_l;
            int cc = n0 + wn + nt * 8 + col_l;
            if (cc >= N) continue;
            float4 a = acc[mt][nt];
            if (vtp != nullptr && (cc & 255) >= 128) {
                int hh = cc >> 8, vd = (cc & 255) - 128;
                int bb = rr >> 11, ss = rr & 2047;
                size_t base = ((size_t)(bb * NH_ + hh) * DV_ + vd) * (size_t)S_;
                vtp[base + ss]          = a.x;
                vtp[base + S_ + ss]     = a.y;
                vtp[base + ss + 8]      = a.z;
                vtp[base + S_ + ss + 8] = a.w;
            } else {
                *(float2*)&C[(size_t)rr * ldc + cc]       = make_float2(a.x, a.y);
                *(float2*)&C[(size_t)(rr + 8) * ldc + cc] = make_float2(a.z, a.w);
            }
        }
    }
}

// ---------------- rmsnorm (in place) ----------------
__global__ __launch_bounds__(256) void rmsnorm_kernel(float* __restrict__ x, int stride, int D,
                                                      const float* __restrict__ w)
{
    int row = blockIdx.x;
    float* p = x + (size_t)row * stride;
    float ss = 0.f;
    for (int i = threadIdx.x; i < D; i += 256) { float v = p[i]; ss += v * v; }
    __shared__ float red[8];
#pragma unroll
    for (int off = 16; off; off >>= 1) ss += __shfl_down_sync(0xffffffffu, ss, off);
    if ((threadIdx.x & 31) == 0) red[threadIdx.x >> 5] = ss;
    __syncthreads();
    if (threadIdx.x == 0) {
        float t = 0.f;
#pragma unroll
        for (int i = 0; i < 8; i++) t += red[i];
        red[0] = rsqrtf(t / (float)D + 1e-6f);
    }
    __syncthreads();
    float inv = red[0];
    for (int i = threadIdx.x; i < D; i += 256) p[i] = p[i] * inv * w[i];
}

// ---------------- RoPE ----------------
__global__ void rope_q_kernel(float* __restrict__ q, const float* __restrict__ cosb,
                              const float* __restrict__ sinb)
{
    int idx = blockIdx.x * blockDim.x + threadIdx.x;
    if (idx >= MTOT * NH_ * 32) return;
    int j = idx & 31;
    int h = (idx >> 5) & (NH_ - 1);
    int m = idx >> 9;
    int s = m & (S_ - 1);
    float* base = q + (size_t)m * QW + h * DQK_ + DN_;
    float x = base[j], y = base[j + 32];
    float c0 = cosb[s * DR_ + j],      s0 = sinb[s * DR_ + j];
    float c1 = cosb[s * DR_ + j + 32], s1 = sinb[s * DR_ + j + 32];
    base[j]      = x * c0 - y * s0;
    base[j + 32] = y * c1 + x * s1;
}

__global__ void rope_k_kernel(float* __restrict__ ckv, const float* __restrict__ cosb,
                              const float* __restrict__ sinb)
{
    int idx = blockIdx.x * blockDim.x + threadIdx.x;
    if (idx >= MTOT * 32) return;
    int j = idx & 31;
    int m = idx >> 5;
    int s = m & (S_ - 1);
    float* base = ckv + (size_t)m * CKVW + KVLR_;
    float x = base[j], y = base[j + 32];
    float c0 = cosb[s * DR_ + j],      s0 = sinb[s * DR_ + j];
    float c1 = cosb[s * DR_ + j + 32], s1 = sinb[s * DR_ + j + 32];
    base[j]      = x * c0 - y * s0;
    base[j + 32] = y * c1 + x * s1;
}

// ---------------- tensor-core flash attention ----------------
#define AQ_LD 196
#define AK_LD 196
#define AV_LD 68
#define AP_LD 68
#define AO_LD 132
#define ATTN_SMEM_FLOATS (64*AQ_LD + 64*AK_LD + 128*AV_LD + 64*AP_LD + 256)
#define ATTN_SMEM_BYTES  (ATTN_SMEM_FLOATS * 4)

__global__ __launch_bounds__(256, 1) void attn_mma(
    const float* __restrict__ q, const float* __restrict__ kv,
    const float* __restrict__ ckv, const float* __restrict__ vt,
    float* __restrict__ ao)
{
    extern __shared__ float sm[];
    float* Qs   = sm;
    float* Kt   = Qs + 64 * AQ_LD;
    float* Vt   = Kt + 64 * AK_LD;
    float* Ps   = Vt + 128 * AV_LD;
    float* mbuf = Ps + 64 * AP_LD;
    float* lbuf = mbuf + 128;

    int qt = blockIdx.x, h = blockIdx.y, b = blockIdx.z;
    int tid = threadIdx.x, warp = tid >> 5, lane = tid & 31;
    int qs = (warp & 3) * 16;
    int kh = warp >> 2;
    int r  = lane >> 2, qd = lane & 3;

    int a_row = ((lane >> 3) & 1) * 8 + (lane & 7);
    int a_col = ((lane >> 4) & 1) * 4;
    uint32_t smem_base = (uint32_t)__cvta_generic_to_shared(sm);
    uint32_t ps_off = (uint32_t)((Ps - sm)) * 4;

    int qbase = b * S_ + qt * 64;

    for (int i = tid; i < 64 * 48; i += 256) {
        int qr = i / 48, dq = (i - qr * 48) * 4;
        float4 v = *(const float4*)&q[(size_t)(qbase + qr) * QW + h * DQK_ + dq];
        uint4 u = make_uint4(f2tf(v.x * SCALE_CONST), f2tf(v.y * SCALE_CONST),
                             f2tf(v.z * SCALE_CONST), f2tf(v.w * SCALE_CONST));
        *(uint4*)&Qs[qr * AQ_LD + dq] = u;
    }

    float4 o[16];
#pragma unroll
    for (int i = 0; i < 16; i++) o[i] = make_float4(0.f, 0.f, 0.f, 0.f);
    float m_r = -1e30f, m_r8 = -1e30f, l_r = 0.f, l_r8 = 0.f;

    const float* vtp = &vt[(size_t)(b * NH_ + h) * DV_ * S_];

    for (int kt = 0; kt <= qt; kt++) {
        __syncthreads();
        int kbase = b * S_ + kt * 64;
        for (int i = tid; i < 64 * 48; i += 256) {
            int kc = i / 48, dq = (i - kc * 48) * 4;
            float4 v;
            if (dq < 128) v = *(const float4*)&kv[(size_t)(kbase + kc) * KVW + h * 256 + dq];
            else          v = *(const float4*)&ckv[(size_t)(kbase + kc) * CKVW + KVLR_ + dq - 128];
            uint4 u = make_uint4(f2tf(v.x), f2tf(v.y), f2tf(v.z), f2tf(v.w));
            *(uint4*)&Kt[kc * AK_LD + dq] = u;
        }
        for (int i = tid; i < 128 * 16; i += 256) {
            int vd = i >> 4, kq = (i & 15) * 4;
            float4 v = *(const float4*)&vtp[(size_t)vd * S_ + kt * 64 + kq];
            uint4 u = make_uint4(f2tf(v.x), f2tf(v.y), f2tf(v.z), f2tf(v.w));
            *(uint4*)&Vt[vd * AV_LD + kq] = u;
        }
        __syncthreads();

        float4 s4[4];
#pragma unroll
        for (int nt = 0; nt < 4; nt++) s4[nt] = make_float4(0.f, 0.f, 0.f, 0.f);
#pragma unroll
        for (int ks = 0; ks < 24; ks++) {
            uint32_t af[4];
            ldsm4(af, smem_base + ((qs + a_row) * AQ_LD + ks * 8 + a_col) * 4);
#pragma unroll
            for (int nt = 0; nt < 4; nt++) {
                const float* p = &Kt[(kh * 32 + nt * 8 + r) * AK_LD + ks * 8 + qd];
                mma_tf32(s4[nt], af, __float_as_uint(p[0]), __float_as_uint(p[4]));
            }
        }

        if (kt == qt) {
#pragma unroll
            for (int nt = 0; nt < 4; nt++) {
                int c0 = kh * 32 + nt * 8 + 2 * qd;
                int row = qs + r;
                if (c0     > row)     s4[nt].x = -1e30f;
                if (c0 + 1 > row)     s4[nt].y = -1e30f;
                if (c0     > row + 8) s4[nt].z = -1e30f;
                if (c0 + 1 > row + 8) s4[nt].w = -1e30f;
            }
        }

        float lm_r = -1e30f, lm_r8 = -1e30f;
#pragma unroll
        for (int nt = 0; nt < 4; nt++) {
            lm_r  = fmaxf(lm_r,  fmaxf(s4[nt].x, s4[nt].y));
            lm_r8 = fmaxf(lm_r8, fmaxf(s4[nt].z, s4[nt].w));
        }
        lm_r  = fmaxf(lm_r,  __shfl_xor_sync(0xffffffffu, lm_r, 1));
        lm_r  = fmaxf(lm_r,  __shfl_xor_sync(0xffffffffu, lm_r, 2));
        lm_r8 = fmaxf(lm_r8, __shfl_xor_sync(0xffffffffu, lm_r8, 1));
        lm_r8 = fmaxf(lm_r8, __shfl_xor_sync(0xffffffffu, lm_r8, 2));
        if (qd == 0) {
            mbuf[kh * 64 + qs + r]     = lm_r;
            mbuf[kh * 64 + qs + r + 8] = lm_r8;
        }
        __syncthreads();
        float mn_r  = fmaxf(m_r,  fmaxf(mbuf[qs + r],     mbuf[64 + qs + r]));
        float mn_r8 = fmaxf(m_r8, fmaxf(mbuf[qs + r + 8], mbuf[64 + qs + r + 8]));
        float al_r  = __expf(m_r - mn_r);
        float al_r8 = __expf(m_r8 - mn_r8);
        m_r = mn_r; m_r8 = mn_r8;

        float ps_r = 0.f, ps_r8 = 0.f;
#pragma unroll
        for (int nt = 0; nt < 4; nt++) {
            float px = __expf(s4[nt].x - mn_r);
            float py = __expf(s4[nt].y - mn_r);
            float pz = __expf(s4[nt].z - mn_r8);
            float pw = __expf(s4[nt].w - mn_r8);
            ps_r  += px + py;
            ps_r8 += pz + pw;
            int col = kh * 32 + nt * 8 + 2 * qd;
            *(uint2*)&Ps[(qs + r) * AP_LD + col]     = make_uint2(f2tf(px), f2tf(py));
            *(uint2*)&Ps[(qs + r + 8) * AP_LD + col] = make_uint2(f2tf(pz), f2tf(pw));
        }
        ps_r  += __shfl_xor_sync(0xffffffffu, ps_r, 1);
        ps_r  += __shfl_xor_sync(0xffffffffu, ps_r, 2);
        ps_r8 += __shfl_xor_sync(0xffffffffu, ps_r8, 1);
        ps_r8 += __shfl_xor_sync(0xffffffffu, ps_r8, 2);
        l_r  = l_r  * al_r  + ps_r;
        l_r8 = l_r8 * al_r8 + ps_r8;
        __syncwarp();

#pragma unroll
        for (int nt = 0; nt < 16; nt++) {
            o[nt].x *= al_r;  o[nt].y *= al_r;
            o[nt].z *= al_r8; o[nt].w *= al_r8;
        }
#pragma unroll
        for (int ks = 0; ks < 4; ks++) {
            uint32_t af[4];
            ldsm4(af, smem_base + ps_off + ((qs + a_row) * AP_LD + kh * 32 + ks * 8 + a_col) * 4);
#pragma unroll
            for (int nt = 0; nt < 16; nt++) {
                const float* p = &Vt[(nt * 8 + r) * AV_LD + kh * 32 + ks * 8 + qd];
                mma_tf32(o[nt], af, __float_as_uint(p[0]), __float_as_uint(p[4]));
            }
        }
    }

    __syncthreads();
    float* obuf = Kt;
    if (qd == 0) {
        lbuf[kh * 64 + qs + r]     = l_r;
        lbuf[kh * 64 + qs + r + 8] = l_r8;
    }
    if (kh == 1) {
#pragma unroll
        for (int nt = 0; nt < 16; nt++) {
            int col = nt * 8 + 2 * qd;
            *(float2*)&obuf[(qs + r) * AO_LD + col]     = make_float2(o[nt].x, o[nt].y);
            *(float2*)&obuf[(qs + r + 8) * AO_LD + col] = make_float2(o[nt].z, o[nt].w);
        }
    }
    __syncthreads();
    if (kh == 0) {
        float inv_r  = 1.f / (lbuf[qs + r]     + lbuf[64 + qs + r]);
        float inv_r8 = 1.f / (lbuf[qs + r + 8] + lbuf[64 + qs + r + 8]);
#pragma unroll
        for (int nt = 0; nt < 16; nt++) {
            int col = nt * 8 + 2 * qd;
            float2 p0 = *(float2*)&obuf[(qs + r) * AO_LD + col];
            float2 p1 = *(float2*)&obuf[(qs + r + 8) * AO_LD + col];
            size_t row0 = (size_t)(qbase + qs + r);
            *(float2*)&ao[row0 * AOW + h * DV_ + col] =
                make_float2((o[nt].x + p0.x) * inv_r, (o[nt].y + p0.y) * inv_r);
            *(float2*)&ao[(row0 + 8) * AOW + h * DV_ + col] =
                make_float2((o[nt].z + p1.x) * inv_r8, (o[nt].w + p1.y) * inv_r8);
        }
    }
}

// ---------------- launch ----------------
extern "C" void kernel_launch(void* const* d_in, const int* in_sizes, int n_in,
                              void* d_out, int out_size)
{
    const float* hidden = (const float*)d_in[0];
    const float* cosb   = (const float*)d_in[2];
    const float* sinb   = (const float*)d_in[3];
    const float* w_qa   = (const float*)d_in[4];
    const float* qa_ln  = (const float*)d_in[5];
    const float* w_qb   = (const float*)d_in[6];
    const float* w_kva  = (const float*)d_in[7];
    const float* kva_ln = (const float*)d_in[8];
    const float* w_kvb  = (const float*)d_in[9];
    const float* w_o    = (const float*)d_in[10];
    float* out = (float*)d_out;

    float *qa, *ckv, *qbuf, *kvbuf, *ao, *vt;
    cudaGetSymbolAddress((void**)&qa,    g_qa);
    cudaGetSymbolAddress((void**)&ckv,   g_ckv);
    cudaGetSymbolAddress((void**)&qbuf,  g_q);
    cudaGetSymbolAddress((void**)&kvbuf, g_kv);
    cudaGetSymbolAddress((void**)&ao,    g_ao);
    cudaGetSymbolAddress((void**)&vt,    g_vt);

    cudaFuncSetAttribute(attn_mma, cudaFuncAttributeMaxDynamicSharedMemorySize,
                         ATTN_SMEM_BYTES);

    // 1. q_a = hidden @ w_qa
    gemm_tf32<<<dim3(QLR_ / 128, MTOT / 128), 256>>>(hidden, HID_, w_qa, QLR_, qa, QLR_,
                                                     MTOT, QLR_, HID_, nullptr);
    // 2. ckv = hidden @ w_kva
    gemm_tf32<<<dim3((CKVW + 127) / 128, MTOT / 128), 256>>>(hidden, HID_, w_kva, CKVW,
                                                             ckv, CKVW, MTOT, CKVW, HID_, nullptr);
    // 3. rmsnorms
    rmsnorm_kernel<<<MTOT, 256>>>(qa, QLR_, QLR_, qa_ln);
    rmsnorm_kernel<<<MTOT, 256>>>(ckv, CKVW, KVLR_, kva_ln);
    // 4. q = qa_norm @ w_qb
    gemm_tf32<<<dim3(QW / 128, MTOT / 128), 256>>>(qa, QLR_, w_qb, QW, qbuf, QW,
                                                   MTOT, QW, QLR_, nullptr);
    // 5. kv = ckv_norm @ w_kvb  (V half scattered transposed into vt)
    gemm_tf32<<<dim3(KVW / 128, MTOT / 128), 256>>>(ckv, CKVW, w_kvb, KVW, kvbuf, KVW,
                                                    MTOT, KVW, KVLR_, vt);
    // 6. RoPE
    rope_q_kernel<<<(MTOT * NH_ * 32 + 255) / 256, 256>>>(qbuf, cosb, sinb);
    rope_k_kernel<<<(MTOT * 32 + 255) / 256, 256>>>(ckv, cosb, sinb);
    // 7. attention (tensor core)
    attn_mma<<<dim3(S_ / 64, NH_, B_), 256, ATTN_SMEM_BYTES>>>(qbuf, kvbuf, ckv, vt, ao);
    // 8. out = ao @ w_o
    gemm_tf32<<<dim3(HID_ / 128, MTOT / 128), 256>>>(ao, AOW, w_o, HID_, out, HID_,
                                                     MTOT, HID_, AOW, nullptr);
}

// round 7
// speedup vs baseline: 4.1910x; 1.2700x over previous
#include <cuda_runtime.h>
#include <math.h>
#include <stdint.h>

#define B_    2
#define S_    2048
#define HID_  2048
#define NH_   16
#define QLR_  1536
#define KVLR_ 512
#define DN_   128
#define DR_   64
#define DV_   128
#define DQK_  192
#define MTOT  (B_ * S_)            // 4096
#define CKVW  (KVLR_ + DR_)        // 576
#define QW    (NH_ * DQK_)         // 3072
#define KVW   (NH_ * (DN_ + DV_))  // 4096
#define AOW   (NH_ * DV_)          // 2048
#define SCALE_CONST 0.07216878364870322f   // 192^-0.5

// ---------------- scratch (no allocation allowed) ----------------
__device__ float g_qa [(size_t)MTOT * QLR_];
__device__ float g_ckv[(size_t)MTOT * CKVW];
__device__ float g_q  [(size_t)MTOT * QW];
__device__ float g_kv [(size_t)MTOT * KVW];
__device__ float g_ao [(size_t)MTOT * AOW];
__device__ float g_vt [(size_t)B_ * NH_ * DV_ * S_];   // V transposed: [b][h][vd][s]

// ---------------- helpers ----------------
__device__ __forceinline__ uint32_t f2tf(float f) {
    uint32_t u;
    asm("cvt.rna.tf32.f32 %0, %1;" : "=r"(u) : "f"(f));
    return u;
}

__device__ __forceinline__ void ldsm4(uint32_t* r, uint32_t addr) {
    asm volatile("ldmatrix.sync.aligned.m8n8.x4.shared.b16 {%0,%1,%2,%3},[%4];"
                 : "=r"(r[0]), "=r"(r[1]), "=r"(r[2]), "=r"(r[3]) : "r"(addr));
}

__device__ __forceinline__ void mma_tf32(float4& d, const uint32_t* a, uint32_t b0, uint32_t b1) {
    asm volatile("mma.sync.aligned.m16n8k8.row.col.f32.tf32.tf32.f32 "
                 "{%0,%1,%2,%3},{%4,%5,%6,%7},{%8,%9},{%0,%1,%2,%3};"
                 : "+f"(d.x), "+f"(d.y), "+f"(d.z), "+f"(d.w)
                 : "r"(a[0]), "r"(a[1]), "r"(a[2]), "r"(a[3]), "r"(b0), "r"(b1));
}

__device__ __forceinline__ void cpa16(uint32_t dst, const void* src) {
    asm volatile("cp.async.cg.shared.global [%0], [%1], 16;" :: "r"(dst), "l"(src));
}
#define CP_COMMIT() asm volatile("cp.async.commit_group;")
#define CP_WAIT0()  asm volatile("cp.async.wait_group 0;")
#define CP_WAIT1()  asm volatile("cp.async.wait_group 1;")

// ---------------- tf32 GEMM: C[M,N] = A[M,K] @ Bm[K,N] ----------------
// BM=128 BN=128 BK=32, 256 threads (8 warps = 2m x 4n), warp tile 64x32.
// 3-stage cp.async pipeline, raw fp32 in smem, tf32 cvt at fragment load.
#define GBM 128
#define GBN 128
#define GBK 32
#define ALD 36
#define BLD 132
#define GEMM_A_FLOATS (GBM * ALD)   // 4608
#define GEMM_B_FLOATS (GBK * BLD)   // 4224
#define GEMM_SMEM_BYTES (3 * (GEMM_A_FLOATS + GEMM_B_FLOATS) * 4)   // 105984

__global__ __launch_bounds__(256, 2) void gemm_tf32(
    const float* __restrict__ A, int lda,
    const float* __restrict__ Bm, int ldb,
    float* __restrict__ C, int ldc,
    int M, int N, int K,
    float* __restrict__ vtp)   // non-null: kvb mode, V half scattered transposed
{
    extern __shared__ float gsm[];
    float* As = gsm;                        // 3 stages of [128][36]
    float* Bs = gsm + 3 * GEMM_A_FLOATS;    // 3 stages of [32][132]

    int tid = threadIdx.x;
    int m0 = blockIdx.y * GBM, n0 = blockIdx.x * GBN;
    int warp = tid >> 5, lane = tid & 31;
    int wm = (warp & 1) * 64, wn = (warp >> 1) * 32;
    int r = lane >> 2, qd = lane & 3;

    float4 acc[4][4];
#pragma unroll
    for (int i = 0; i < 4; i++)
#pragma unroll
        for (int j = 0; j < 4; j++) acc[i][j] = make_float4(0.f, 0.f, 0.f, 0.f);

    int a_row = ((lane >> 3) & 1) * 8 + (lane & 7);
    int a_col = ((lane >> 4) & 1) * 4;
    uint32_t as_u = (uint32_t)__cvta_generic_to_shared(As);
    uint32_t bs_u = (uint32_t)__cvta_generic_to_shared(Bs);

    // staging geometry (all cp.async 16B)
    int s_arow = tid >> 3, s_akc = (tid & 7) * 4;    // A: 4 chunks, rows +32
    int s_krow = tid >> 5, bnc = (lane & 31) * 4;    // B: 4 chunks, k-rows +8
    bool nok = (n0 + bnc) < N;

    int nk = K / GBK;

#define GEMM_ISSUE(stage, k0)                                                      \
    do {                                                                           \
        uint32_t ad = as_u + (uint32_t)(stage) * GEMM_A_FLOATS * 4;                \
        uint32_t bd = bs_u + (uint32_t)(stage) * GEMM_B_FLOATS * 4;                \
        _Pragma("unroll")                                                          \
        for (int it = 0; it < 4; it++) {                                           \
            int row = s_arow + it * 32;                                            \
            cpa16(ad + (row * ALD + s_akc) * 4,                                    \
                  &A[(size_t)(m0 + row) * lda + (k0) + s_akc]);                    \
        }                                                                          \
        if (nok) {                                                                 \
            _Pragma("unroll")                                                      \
            for (int it = 0; it < 4; it++) {                                       \
                int kk2 = s_krow + it * 8;                                         \
                cpa16(bd + (kk2 * BLD + bnc) * 4,                                  \
                      &Bm[(size_t)((k0) + kk2) * ldb + n0 + bnc]);                 \
            }                                                                      \
        }                                                                          \
    } while (0)

    GEMM_ISSUE(0, 0);
    CP_COMMIT();
    if (nk > 1) GEMM_ISSUE(1, GBK);
    CP_COMMIT();

    for (int t = 0; t < nk; t++) {
        CP_WAIT1();
        __syncthreads();
        if (t + 2 < nk) GEMM_ISSUE((t + 2) % 3, (t + 2) * GBK);
        CP_COMMIT();

        int s = t % 3;
        uint32_t a_base = as_u + (uint32_t)s * GEMM_A_FLOATS * 4;
        const float* bsp = Bs + s * GEMM_B_FLOATS;

#pragma unroll
        for (int ks = 0; ks < 4; ks++) {
            int kk = ks * 8;
            uint32_t af[4][4];
#pragma unroll
            for (int mt = 0; mt < 4; mt++) {
                ldsm4(af[mt], a_base + ((wm + mt * 16 + a_row) * ALD + kk + a_col) * 4);
#pragma unroll
                for (int i = 0; i < 4; i++)
                    af[mt][i] = f2tf(__uint_as_float(af[mt][i]));
            }
            uint32_t b0[4], b1[4];
#pragma unroll
            for (int nt = 0; nt < 4; nt++) {
                const float* p = &bsp[(kk + qd) * BLD + wn + nt * 8 + r];
                b0[nt] = f2tf(p[0]);
                b1[nt] = f2tf(p[4 * BLD]);
            }
#pragma unroll
            for (int mt = 0; mt < 4; mt++)
#pragma unroll
                for (int nt = 0; nt < 4; nt++)
                    mma_tf32(acc[mt][nt], af[mt], b0[nt], b1[nt]);
        }
    }
#undef GEMM_ISSUE

    int row_l = lane >> 2, col_l = (lane & 3) * 2;
#pragma unroll
    for (int mt = 0; mt < 4; mt++) {
#pragma unroll
        for (int nt = 0; nt < 4; nt++) {
            int rr = m0 + wm + mt * 16 + row_l;
            int cc = n0 + wn + nt * 8 + col_l;
            if (cc >= N) continue;
            float4 a = acc[mt][nt];
            if (vtp != nullptr && (cc & 255) >= 128) {
                int hh = cc >> 8, vd = (cc & 255) - 128;
                int bb = rr >> 11, ss = rr & 2047;
                size_t base = ((size_t)(bb * NH_ + hh) * DV_ + vd) * (size_t)S_;
                vtp[base + ss]          = a.x;
                vtp[base + S_ + ss]     = a.y;
                vtp[base + ss + 8]      = a.z;
                vtp[base + S_ + ss + 8] = a.w;
            } else {
                *(float2*)&C[(size_t)rr * ldc + cc]       = make_float2(a.x, a.y);
                *(float2*)&C[(size_t)(rr + 8) * ldc + cc] = make_float2(a.z, a.w);
            }
        }
    }
}

// ---------------- rmsnorm (in place) ----------------
__global__ __launch_bounds__(256) void rmsnorm_kernel(float* __restrict__ x, int stride, int D,
                                                      const float* __restrict__ w)
{
    int row = blockIdx.x;
    float* p = x + (size_t)row * stride;
    float ss = 0.f;
    for (int i = threadIdx.x; i < D; i += 256) { float v = p[i]; ss += v * v; }
    __shared__ float red[8];
#pragma unroll
    for (int off = 16; off; off >>= 1) ss += __shfl_down_sync(0xffffffffu, ss, off);
    if ((threadIdx.x & 31) == 0) red[threadIdx.x >> 5] = ss;
    __syncthreads();
    if (threadIdx.x == 0) {
        float t = 0.f;
#pragma unroll
        for (int i = 0; i < 8; i++) t += red[i];
        red[0] = rsqrtf(t / (float)D + 1e-6f);
    }
    __syncthreads();
    float inv = red[0];
    for (int i = threadIdx.x; i < D; i += 256) p[i] = p[i] * inv * w[i];
}

// ---------------- RoPE ----------------
__global__ void rope_q_kernel(float* __restrict__ q, const float* __restrict__ cosb,
                              const float* __restrict__ sinb)
{
    int idx = blockIdx.x * blockDim.x + threadIdx.x;
    if (idx >= MTOT * NH_ * 32) return;
    int j = idx & 31;
    int h = (idx >> 5) & (NH_ - 1);
    int m = idx >> 9;
    int s = m & (S_ - 1);
    float* base = q + (size_t)m * QW + h * DQK_ + DN_;
    float x = base[j], y = base[j + 32];
    float c0 = cosb[s * DR_ + j],      s0 = sinb[s * DR_ + j];
    float c1 = cosb[s * DR_ + j + 32], s1 = sinb[s * DR_ + j + 32];
    base[j]      = x * c0 - y * s0;
    base[j + 32] = y * c1 + x * s1;
}

__global__ void rope_k_kernel(float* __restrict__ ckv, const float* __restrict__ cosb,
                              const float* __restrict__ sinb)
{
    int idx = blockIdx.x * blockDim.x + threadIdx.x;
    if (idx >= MTOT * 32) return;
    int j = idx & 31;
    int m = idx >> 5;
    int s = m & (S_ - 1);
    float* base = ckv + (size_t)m * CKVW + KVLR_;
    float x = base[j], y = base[j + 32];
    float c0 = cosb[s * DR_ + j],      s0 = sinb[s * DR_ + j];
    float c1 = cosb[s * DR_ + j + 32], s1 = sinb[s * DR_ + j + 32];
    base[j]      = x * c0 - y * s0;
    base[j + 32] = y * c1 + x * s1;
}

// ---------------- tensor-core flash attention (cp.async pipelined) ----------------
#define AQ_LD 196
#define AK_LD 196
#define AV_LD 68
#define AP_LD 68
#define AO_LD 132
// Q[64][196] + K0[64][196] + K1[64][196] + V[128][68] + P[64][68] + 256
#define ATTN_SMEM_FLOATS (3 * 64 * AQ_LD + 128 * AV_LD + 64 * AP_LD + 256)
#define ATTN_SMEM_BYTES  (ATTN_SMEM_FLOATS * 4)

__global__ __launch_bounds__(256, 1) void attn_mma(
    const float* __restrict__ q, const float* __restrict__ kv,
    const float* __restrict__ ckv, const float* __restrict__ vt,
    float* __restrict__ ao)
{
    extern __shared__ float sm[];
    float* Qs   = sm;                     // [64][196] tf32 (pre-converted)
    float* K0   = Qs + 64 * AQ_LD;        // [64][196] raw fp32 (cp.async)
    float* K1   = K0 + 64 * AK_LD;
    float* Vt   = K1 + 64 * AK_LD;        // [128][68] raw fp32 (cp.async)
    float* Ps   = Vt + 128 * AV_LD;       // [64][68]  tf32
    float* mbuf = Ps + 64 * AP_LD;        // [2][64]
    float* lbuf = mbuf + 128;             // [2][64]

    int qt = blockIdx.x, h = blockIdx.y, b = blockIdx.z;
    int tid = threadIdx.x, warp = tid >> 5, lane = tid & 31;
    int qs = (warp & 3) * 16;
    int kh = warp >> 2;
    int r  = lane >> 2, qd = lane & 3;

    int a_row = ((lane >> 3) & 1) * 8 + (lane & 7);
    int a_col = ((lane >> 4) & 1) * 4;
    uint32_t smem_base = (uint32_t)__cvta_generic_to_shared(sm);
    uint32_t ps_off = (uint32_t)((Ps - sm)) * 4;
    uint32_t k0_u = (uint32_t)__cvta_generic_to_shared(K0);
    uint32_t k1_u = (uint32_t)__cvta_generic_to_shared(K1);
    uint32_t vt_u = (uint32_t)__cvta_generic_to_shared(Vt);

    int qbase = b * S_ + qt * 64;
    const float* vtp = &vt[(size_t)(b * NH_ + h) * DV_ * S_];

    // K issue: 64 rows x 48 float4-chunks (32 from kv, 16 from roped ckv) = 12/thread
#define ATTN_ISSUE_K(ktile, kdst_u)                                                \
    do {                                                                           \
        int kb2 = b * S_ + (ktile) * 64;                                           \
        _Pragma("unroll")                                                          \
        for (int i = 0; i < 12; i++) {                                             \
            int c = tid + i * 256;                                                 \
            int row = c / 48, j = c - row * 48;                                    \
            const float* src = (j < 32)                                            \
                ? &kv[(size_t)(kb2 + row) * KVW + h * 256 + j * 4]                 \
                : &ckv[(size_t)(kb2 + row) * CKVW + KVLR_ + (j - 32) * 4];         \
            cpa16((kdst_u) + (row * AK_LD + j * 4) * 4, src);                      \
        }                                                                          \
    } while (0)

    // V issue: 128 vd-rows x 16 float4-chunks = 8/thread
#define ATTN_ISSUE_V(ktile)                                                        \
    do {                                                                           \
        _Pragma("unroll")                                                          \
        for (int i = 0; i < 8; i++) {                                              \
            int c = tid + i * 256;                                                 \
            int vd = c >> 4, j = c & 15;                                           \
            cpa16(vt_u + (vd * AV_LD + j * 4) * 4,                                 \
                  &vtp[(size_t)vd * S_ + (ktile) * 64 + j * 4]);                   \
        }                                                                          \
    } while (0)

    // stage Q (scaled, tf32) with regular loads
    for (int i = tid; i < 64 * 48; i += 256) {
        int qr = i / 48, dq = (i - qr * 48) * 4;
        float4 v = *(const float4*)&q[(size_t)(qbase + qr) * QW + h * DQK_ + dq];
        uint4 u = make_uint4(f2tf(v.x * SCALE_CONST), f2tf(v.y * SCALE_CONST),
                             f2tf(v.z * SCALE_CONST), f2tf(v.w * SCALE_CONST));
        *(uint4*)&Qs[qr * AQ_LD + dq] = u;
    }

    // prologue: K(0)
    ATTN_ISSUE_K(0, k0_u);
    CP_COMMIT();

    float4 o[16];
#pragma unroll
    for (int i = 0; i < 16; i++) o[i] = make_float4(0.f, 0.f, 0.f, 0.f);
    float m_r = -1e30f, m_r8 = -1e30f, l_r = 0.f, l_r8 = 0.f;

    for (int kt = 0; kt <= qt; kt++) {
        __syncthreads();   // close previous tile's smem reads (V, K buffers)
        if (kt + 1 <= qt) ATTN_ISSUE_K(kt + 1, ((kt + 1) & 1) ? k1_u : k0_u);
        ATTN_ISSUE_V(kt);
        CP_COMMIT();
        CP_WAIT1();        // K(kt) complete (this thread)
        __syncthreads();   // K(kt) visible to all

        const float* Kb = (kt & 1) ? K1 : K0;

        // S = Q @ K^T  (warp: 16 rows x 32 cols of its half)
        float4 s4[4];
#pragma unroll
        for (int nt = 0; nt < 4; nt++) s4[nt] = make_float4(0.f, 0.f, 0.f, 0.f);
#pragma unroll
        for (int ks = 0; ks < 24; ks++) {
            uint32_t af[4];
            ldsm4(af, smem_base + ((qs + a_row) * AQ_LD + ks * 8 + a_col) * 4);
#pragma unroll
            for (int nt = 0; nt < 4; nt++) {
                const float* p = &Kb[(kh * 32 + nt * 8 + r) * AK_LD + ks * 8 + qd];
                mma_tf32(s4[nt], af, f2tf(p[0]), f2tf(p[4]));
            }
        }

        if (kt == qt) {
#pragma unroll
            for (int nt = 0; nt < 4; nt++) {
                int c0 = kh * 32 + nt * 8 + 2 * qd;
                int row = qs + r;
                if (c0     > row)     s4[nt].x = -1e30f;
                if (c0 + 1 > row)     s4[nt].y = -1e30f;
                if (c0     > row + 8) s4[nt].z = -1e30f;
                if (c0 + 1 > row + 8) s4[nt].w = -1e30f;
            }
        }

        float lm_r = -1e30f, lm_r8 = -1e30f;
#pragma unroll
        for (int nt = 0; nt < 4; nt++) {
            lm_r  = fmaxf(lm_r,  fmaxf(s4[nt].x, s4[nt].y));
            lm_r8 = fmaxf(lm_r8, fmaxf(s4[nt].z, s4[nt].w));
        }
        lm_r  = fmaxf(lm_r,  __shfl_xor_sync(0xffffffffu, lm_r, 1));
        lm_r  = fmaxf(lm_r,  __shfl_xor_sync(0xffffffffu, lm_r, 2));
        lm_r8 = fmaxf(lm_r8, __shfl_xor_sync(0xffffffffu, lm_r8, 1));
        lm_r8 = fmaxf(lm_r8, __shfl_xor_sync(0xffffffffu, lm_r8, 2));
        if (qd == 0) {
            mbuf[kh * 64 + qs + r]     = lm_r;
            mbuf[kh * 64 + qs + r + 8] = lm_r8;
        }
        CP_WAIT0();        // V(kt) complete (this thread)
        __syncthreads();   // mbuf + V visible to all
        float mn_r  = fmaxf(m_r,  fmaxf(mbuf[qs + r],     mbuf[64 + qs + r]));
        float mn_r8 = fmaxf(m_r8, fmaxf(mbuf[qs + r + 8], mbuf[64 + qs + r + 8]));
        float al_r  = __expf(m_r - mn_r);
        float al_r8 = __expf(m_r8 - mn_r8);
        m_r = mn_r; m_r8 = mn_r8;

        float ps_r = 0.f, ps_r8 = 0.f;
#pragma unroll
        for (int nt = 0; nt < 4; nt++) {
            float px = __expf(s4[nt].x - mn_r);
            float py = __expf(s4[nt].y - mn_r);
            float pz = __expf(s4[nt].z - mn_r8);
            float pw = __expf(s4[nt].w - mn_r8);
            ps_r  += px + py;
            ps_r8 += pz + pw;
            int col = kh * 32 + nt * 8 + 2 * qd;
            *(uint2*)&Ps[(qs + r) * AP_LD + col]     = make_uint2(f2tf(px), f2tf(py));
            *(uint2*)&Ps[(qs + r + 8) * AP_LD + col] = make_uint2(f2tf(pz), f2tf(pw));
        }
        ps_r  += __shfl_xor_sync(0xffffffffu, ps_r, 1);
        ps_r  += __shfl_xor_sync(0xffffffffu, ps_r, 2);
        ps_r8 += __shfl_xor_sync(0xffffffffu, ps_r8, 1);
        ps_r8 += __shfl_xor_sync(0xffffffffu, ps_r8, 2);
        l_r  = l_r  * al_r  + ps_r;
        l_r8 = l_r8 * al_r8 + ps_r8;
        __syncwarp();

#pragma unroll
        for (int nt = 0; nt < 16; nt++) {
            o[nt].x *= al_r;  o[nt].y *= al_r;
            o[nt].z *= al_r8; o[nt].w *= al_r8;
        }
#pragma unroll
        for (int ks = 0; ks < 4; ks++) {
            uint32_t af[4];
            ldsm4(af, smem_base + ps_off + ((qs + a_row) * AP_LD + kh * 32 + ks * 8 + a_col) * 4);
#pragma unroll
            for (int nt = 0; nt < 16; nt++) {
                const float* p = &Vt[(nt * 8 + r) * AV_LD + kh * 32 + ks * 8 + qd];
                mma_tf32(o[nt], af, f2tf(p[0]), f2tf(p[4]));
            }
        }
    }
#undef ATTN_ISSUE_K
#undef ATTN_ISSUE_V

    // combine the two kc-halves
    __syncthreads();
    float* obuf = K0;   // reuse
    if (qd == 0) {
        lbuf[kh * 64 + qs + r]     = l_r;
        lbuf[kh * 64 + qs + r + 8] = l_r8;
    }
    if (kh == 1) {
#pragma unroll
        for (int nt = 0; nt < 16; nt++) {
            int col = nt * 8 + 2 * qd;
            *(float2*)&obuf[(qs + r) * AO_LD + col]     = make_float2(o[nt].x, o[nt].y);
            *(float2*)&obuf[(qs + r + 8) * AO_LD + col] = make_float2(o[nt].z, o[nt].w);
        }
    }
    __syncthreads();
    if (kh == 0) {
        float inv_r  = 1.f / (lbuf[qs + r]     + lbuf[64 + qs + r]);
        float inv_r8 = 1.f / (lbuf[qs + r + 8] + lbuf[64 + qs + r + 8]);
#pragma unroll
        for (int nt = 0; nt < 16; nt++) {
            int col = nt * 8 + 2 * qd;
            float2 p0 = *(float2*)&obuf[(qs + r) * AO_LD + col];
            float2 p1 = *(float2*)&obuf[(qs + r + 8) * AO_LD + col];
            size_t row0 = (size_t)(qbase + qs + r);
            *(float2*)&ao[row0 * AOW + h * DV_ + col] =
                make_float2((o[nt].x + p0.x) * inv_r, (o[nt].y + p0.y) * inv_r);
            *(float2*)&ao[(row0 + 8) * AOW + h * DV_ + col] =
                make_float2((o[nt].z + p1.x) * inv_r8, (o[nt].w + p1.y) * inv_r8);
        }
    }
}

// ---------------- launch ----------------
extern "C" void kernel_launch(void* const* d_in, const int* in_sizes, int n_in,
                              void* d_out, int out_size)
{
    const float* hidden = (const float*)d_in[0];
    const float* cosb   = (const float*)d_in[2];
    const float* sinb   = (const float*)d_in[3];
    const float* w_qa   = (const float*)d_in[4];
    const float* qa_ln  = (const float*)d_in[5];
    const float* w_qb   = (const float*)d_in[6];
    const float* w_kva  = (const float*)d_in[7];
    const float* kva_ln = (const float*)d_in[8];
    const float* w_kvb  = (const float*)d_in[9];
    const float* w_o    = (const float*)d_in[10];
    float* out = (float*)d_out;

    float *qa, *ckv, *qbuf, *kvbuf, *ao, *vt;
    cudaGetSymbolAddress((void**)&qa,    g_qa);
    cudaGetSymbolAddress((void**)&ckv,   g_ckv);
    cudaGetSymbolAddress((void**)&qbuf,  g_q);
    cudaGetSymbolAddress((void**)&kvbuf, g_kv);
    cudaGetSymbolAddress((void**)&ao,    g_ao);
    cudaGetSymbolAddress((void**)&vt,    g_vt);

    cudaFuncSetAttribute(attn_mma, cudaFuncAttributeMaxDynamicSharedMemorySize,
                         ATTN_SMEM_BYTES);
    cudaFuncSetAttribute(gemm_tf32, cudaFuncAttributeMaxDynamicSharedMemorySize,
                         GEMM_SMEM_BYTES);

    // 1. q_a = hidden @ w_qa
    gemm_tf32<<<dim3(QLR_ / 128, MTOT / 128), 256, GEMM_SMEM_BYTES>>>(
        hidden, HID_, w_qa, QLR_, qa, QLR_, MTOT, QLR_, HID_, nullptr);
    // 2. ckv = hidden @ w_kva
    gemm_tf32<<<dim3((CKVW + 127) / 128, MTOT / 128), 256, GEMM_SMEM_BYTES>>>(
        hidden, HID_, w_kva, CKVW, ckv, CKVW, MTOT, CKVW, HID_, nullptr);
    // 3. rmsnorms
    rmsnorm_kernel<<<MTOT, 256>>>(qa, QLR_, QLR_, qa_ln);
    rmsnorm_kernel<<<MTOT, 256>>>(ckv, CKVW, KVLR_, kva_ln);
    // 4. q = qa_norm @ w_qb
    gemm_tf32<<<dim3(QW / 128, MTOT / 128), 256, GEMM_SMEM_BYTES>>>(
        qa, QLR_, w_qb, QW, qbuf, QW, MTOT, QW, QLR_, nullptr);
    // 5. kv = ckv_norm @ w_kvb  (V half scattered transposed into vt)
    gemm_tf32<<<dim3(KVW / 128, MTOT / 128), 256, GEMM_SMEM_BYTES>>>(
        ckv, CKVW, w_kvb, KVW, kvbuf, KVW, MTOT, KVW, KVLR_, vt);
    // 6. RoPE
    rope_q_kernel<<<(MTOT * NH_ * 32 + 255) / 256, 256>>>(qbuf, cosb, sinb);
    rope_k_kernel<<<(MTOT * 32 + 255) / 256, 256>>>(ckv, cosb, sinb);
    // 7. attention (tensor core, cp.async pipelined)
    attn_mma<<<dim3(S_ / 64, NH_, B_), 256, ATTN_SMEM_BYTES>>>(qbuf, kvbuf, ckv, vt, ao);
    // 8. out = ao @ w_o
    gemm_tf32<<<dim3(HID_ / 128, MTOT / 128), 256, GEMM_SMEM_BYTES>>>(
        ao, AOW, w_o, HID_, out, HID_, MTOT, HID_, AOW, nullptr);
}